// round 8
// baseline (speedup 1.0000x reference)
#include <cuda_runtime.h>
#include <cuda_bf16.h>
#include <cstdint>

// ---------------- problem constants ----------------
constexpr int BATCH = 2;
constexpr int NTOK  = 2048;
constexpr int CDIM  = 1024;
constexpr int HEADS = 16;
constexpr int HDIM  = 64;
constexpr int MROWS = BATCH * NTOK;     // 4096
constexpr int QKVC  = 3 * CDIM;         // 3072

// ---------------- scratch (device globals, no allocation) ----------------
__device__ __nv_bfloat16 g_x_hi[MROWS * CDIM];
__device__ __nv_bfloat16 g_x_lo[MROWS * CDIM];
__device__ __nv_bfloat16 g_Wq_hi[QKVC * CDIM];
__device__ __nv_bfloat16 g_Wq_lo[QKVC * CDIM];
__device__ __nv_bfloat16 g_Wp_hi[CDIM * CDIM];
__device__ __nv_bfloat16 g_Wp_lo[CDIM * CDIM];
__device__ __nv_bfloat16 g_q_hi[MROWS * CDIM];
__device__ __nv_bfloat16 g_q_lo[MROWS * CDIM];
__device__ __nv_bfloat16 g_k_hi[MROWS * CDIM];
__device__ __nv_bfloat16 g_k_lo[MROWS * CDIM];
__device__ __nv_bfloat16 g_v_hi[MROWS * CDIM];
__device__ __nv_bfloat16 g_v_lo[MROWS * CDIM];
__device__ __nv_bfloat16 g_c_hi[MROWS * CDIM];
__device__ __nv_bfloat16 g_c_lo[MROWS * CDIM];

// ---------------- helpers ----------------
__device__ __forceinline__ void split2(float v, __nv_bfloat16& h, __nv_bfloat16& l)
{
    h = __float2bfloat16_rn(v);
    l = __float2bfloat16_rn(v - __bfloat162float(h));
}

__device__ __forceinline__ uint32_t smem_u32(const void* p)
{
    uint32_t a;
    asm("{ .reg .u64 t; cvta.to.shared.u64 t, %1; cvt.u32.u64 %0, t; }" : "=r"(a) : "l"(p));
    return a;
}

__device__ __forceinline__ void cp_async16(uint32_t dst, const void* src)
{
    asm volatile("cp.async.cg.shared.global [%0], [%1], 16;" :: "r"(dst), "l"(src));
}

__device__ __forceinline__ void ldsm_x4(uint32_t& r0, uint32_t& r1, uint32_t& r2, uint32_t& r3,
                                        uint32_t addr)
{
    asm volatile("ldmatrix.sync.aligned.m8n8.x4.shared.b16 {%0,%1,%2,%3}, [%4];"
                 : "=r"(r0), "=r"(r1), "=r"(r2), "=r"(r3) : "r"(addr));
}

__device__ __forceinline__ void ldsm_x4_t(uint32_t& r0, uint32_t& r1, uint32_t& r2, uint32_t& r3,
                                          uint32_t addr)
{
    asm volatile("ldmatrix.sync.aligned.m8n8.x4.trans.shared.b16 {%0,%1,%2,%3}, [%4];"
                 : "=r"(r0), "=r"(r1), "=r"(r2), "=r"(r3) : "r"(addr));
}

__device__ __forceinline__ void mma_bf16(float* c, const uint32_t* a, const uint32_t* b)
{
    asm volatile("mma.sync.aligned.m16n8k16.row.col.f32.bf16.bf16.f32 "
                 "{%0,%1,%2,%3}, {%4,%5,%6,%7}, {%8,%9}, {%0,%1,%2,%3};"
                 : "+f"(c[0]), "+f"(c[1]), "+f"(c[2]), "+f"(c[3])
                 : "r"(a[0]), "r"(a[1]), "r"(a[2]), "r"(a[3]), "r"(b[0]), "r"(b[1]));
}

__device__ __forceinline__ float ex2(float x)
{
    float r;
    asm("ex2.approx.ftz.f32 %0, %1;" : "=f"(r) : "f"(x));
    return r;
}

// ---------------- conversion kernel ----------------
__global__ void cvt_x_kernel(const float* __restrict__ x)
{
    int i = blockIdx.x * blockDim.x + threadIdx.x;
    if (i < MROWS * CDIM) split2(x[i], g_x_hi[i], g_x_lo[i]);
}

// ---------------- weight fusion + split: Weff = W + 2 * B @ A ----------------
__device__ __forceinline__ void fuse_body(const float* __restrict__ W,
                                          const float* __restrict__ Bm,
                                          const float* __restrict__ A,
                                          __nv_bfloat16* __restrict__ Whi,
                                          __nv_bfloat16* __restrict__ Wlo, int total)
{
    int idx = blockIdx.x * blockDim.x + threadIdx.x;
    if (idx >= total) return;
    int i = idx >> 10;
    int j = idx & 1023;
    float s = 0.f;
#pragma unroll
    for (int r = 0; r < 16; r++) s += Bm[i * 16 + r] * A[r * CDIM + j];
    split2(W[idx] + 2.0f * s, Whi[idx], Wlo[idx]);
}

__global__ void fuse_qkv_kernel(const float* __restrict__ W, const float* __restrict__ Bm,
                                const float* __restrict__ A)
{
    fuse_body(W, Bm, A, g_Wq_hi, g_Wq_lo, QKVC * CDIM);
}

__global__ void fuse_p_kernel(const float* __restrict__ W, const float* __restrict__ Bm,
                              const float* __restrict__ A)
{
    fuse_body(W, Bm, A, g_Wp_hi, g_Wp_lo, CDIM * CDIM);
}

// ---------------- HMMA GEMM (128x128 tile, 8 warps, 3-term split bf16) --------------
// 4-stage cp.async pipeline, one __syncthreads per K-chunk.
constexpr int GM_RS    = 80;
constexpr int GM_ARR   = 128 * GM_RS;        // 10240
constexpr int GM_STAGE = 4 * GM_ARR;         // 40960
constexpr int GM_NST   = 4;
constexpr int GM_SMEM  = GM_NST * GM_STAGE;  // 163840
constexpr int KCH      = 32;
constexpr int NCHUNK   = 1024 / KCH;         // 32

__device__ __forceinline__ void gm_load_chunk(uint32_t su, int tid,
                                              const __nv_bfloat16* const* srcs, int c)
{
    uint32_t stage = su + (uint32_t)(c & (GM_NST - 1)) * GM_STAGE;
    int k0 = c * KCH;
#pragma unroll
    for (int i = 0; i < 8; i++) {
        int g = i * 256 + tid;
        int t = g >> 9;
        int e = g & 511;
        int r = e >> 2;
        int c16 = e & 3;
        cp_async16(stage + t * GM_ARR + r * GM_RS + c16 * 16,
                   srcs[t] + (size_t)r * 1024 + k0 + c16 * 8);
    }
    asm volatile("cp.async.commit_group;");
}

template <bool QKV_SPLIT_OUT>
__device__ __forceinline__ void mma_gemm_body(const __nv_bfloat16* __restrict__ Ahi,
                                              const __nv_bfloat16* __restrict__ Alo,
                                              const __nv_bfloat16* __restrict__ Bhi,
                                              const __nv_bfloat16* __restrict__ Blo,
                                              const float* __restrict__ bias,
                                              float* __restrict__ C, int Nc)
{
    extern __shared__ char smem[];
    const uint32_t su = smem_u32(smem);
    const int tid = threadIdx.x;
    const int wid = tid >> 5, lane = tid & 31;
    const int warp_m = wid >> 2, warp_n = wid & 3;
    const int row0 = blockIdx.y * 128;
    const int col0 = blockIdx.x * 128;

    const __nv_bfloat16* srcs[4] = {
        Ahi + (size_t)row0 * 1024, Alo + (size_t)row0 * 1024,
        Bhi + (size_t)col0 * 1024, Blo + (size_t)col0 * 1024 };

    float acc[4][4][4];
#pragma unroll
    for (int mt = 0; mt < 4; mt++)
#pragma unroll
        for (int nt = 0; nt < 4; nt++)
#pragma unroll
            for (int f = 0; f < 4; f++) acc[mt][nt][f] = 0.f;

    gm_load_chunk(su, tid, srcs, 0);
    gm_load_chunk(su, tid, srcs, 1);
    gm_load_chunk(su, tid, srcs, 2);

    const int a_row = warp_m * 64 + (lane & 15);
    const int a_kb  = (lane >> 4) << 4;
    const int b_row = warp_n * 32 + ((lane & 7) | ((lane & 16) >> 1));
    const int b_kb  = (lane & 8) << 1;

    for (int c = 0; c < NCHUNK; c++) {
        if (c < NCHUNK - 2)       asm volatile("cp.async.wait_group 2;" ::: "memory");
        else if (c == NCHUNK - 2) asm volatile("cp.async.wait_group 1;" ::: "memory");
        else                      asm volatile("cp.async.wait_group 0;" ::: "memory");
        __syncthreads();
        if (c + 3 < NCHUNK) gm_load_chunk(su, tid, srcs, c + 3);

        const uint32_t stage = su + (uint32_t)(c & (GM_NST - 1)) * GM_STAGE;
#pragma unroll
        for (int ks = 0; ks < 2; ks++) {
            const uint32_t koff = ks * 32;

            uint32_t ah[4][4], al[4][4];
#pragma unroll
            for (int mt = 0; mt < 4; mt++) {
                uint32_t base = (uint32_t)((a_row + mt * 16) * GM_RS + a_kb + koff);
                ldsm_x4(ah[mt][0], ah[mt][1], ah[mt][2], ah[mt][3], stage + 0 * GM_ARR + base);
                ldsm_x4(al[mt][0], al[mt][1], al[mt][2], al[mt][3], stage + 1 * GM_ARR + base);
            }
            uint32_t bh[4][2], bl[4][2];
#pragma unroll
            for (int np = 0; np < 2; np++) {
                uint32_t base = (uint32_t)((b_row + np * 16) * GM_RS + b_kb + koff);
                uint32_t r0, r1, r2, r3;
                ldsm_x4(r0, r1, r2, r3, stage + 2 * GM_ARR + base);
                bh[np * 2][0] = r0; bh[np * 2][1] = r1;
                bh[np * 2 + 1][0] = r2; bh[np * 2 + 1][1] = r3;
                ldsm_x4(r0, r1, r2, r3, stage + 3 * GM_ARR + base);
                bl[np * 2][0] = r0; bl[np * 2][1] = r1;
                bl[np * 2 + 1][0] = r2; bl[np * 2 + 1][1] = r3;
            }
#pragma unroll
            for (int mt = 0; mt < 4; mt++)
#pragma unroll
                for (int nt = 0; nt < 4; nt++) {
                    mma_bf16(acc[mt][nt], ah[mt], bh[nt]);
                    mma_bf16(acc[mt][nt], al[mt], bh[nt]);
                    mma_bf16(acc[mt][nt], ah[mt], bl[nt]);
                }
        }
    }

    if (!QKV_SPLIT_OUT) {
#pragma unroll
        for (int mt = 0; mt < 4; mt++) {
            int rg = row0 + warp_m * 64 + mt * 16 + (lane >> 2);
#pragma unroll
            for (int nt = 0; nt < 4; nt++) {
                int cg = col0 + warp_n * 32 + nt * 8 + (lane & 3) * 2;
                float b0 = bias[cg], b1 = bias[cg + 1];
                float2 v0 = make_float2(acc[mt][nt][0] + b0, acc[mt][nt][1] + b1);
                float2 v1 = make_float2(acc[mt][nt][2] + b0, acc[mt][nt][3] + b1);
                *reinterpret_cast<float2*>(&C[(size_t)rg * Nc + cg]) = v0;
                *reinterpret_cast<float2*>(&C[(size_t)(rg + 8) * Nc + cg]) = v1;
            }
        }
    } else {
        __nv_bfloat162* hiA[3] = { reinterpret_cast<__nv_bfloat162*>(g_q_hi),
                                   reinterpret_cast<__nv_bfloat162*>(g_k_hi),
                                   reinterpret_cast<__nv_bfloat162*>(g_v_hi) };
        __nv_bfloat162* loA[3] = { reinterpret_cast<__nv_bfloat162*>(g_q_lo),
                                   reinterpret_cast<__nv_bfloat162*>(g_k_lo),
                                   reinterpret_cast<__nv_bfloat162*>(g_v_lo) };
#pragma unroll
        for (int nt = 0; nt < 4; nt++) {
            int cg = col0 + warp_n * 32 + nt * 8 + (lane & 3) * 2;
            int which = cg >> 10;
            int rem = cg & 1023;
            int h = rem >> 6;
            int d = rem & 63;
            float b0 = bias[cg], b1 = bias[cg + 1];
#pragma unroll
            for (int mt = 0; mt < 4; mt++) {
                int rbase = row0 + warp_m * 64 + mt * 16 + (lane >> 2);
#pragma unroll
                for (int half = 0; half < 2; half++) {
                    int r = rbase + half * 8;
                    int bb = r >> 11, n = r & 2047;
                    size_t di = (((size_t)((bb << 4) + h) * 2048 + n) * 64 + d) >> 1;
                    float v0 = acc[mt][nt][half * 2 + 0] + b0;
                    float v1 = acc[mt][nt][half * 2 + 1] + b1;
                    __nv_bfloat16 h0, l0, h1, l1;
                    split2(v0, h0, l0);
                    split2(v1, h1, l1);
                    hiA[which][di] = __nv_bfloat162(h0, h1);
                    loA[which][di] = __nv_bfloat162(l0, l1);
                }
            }
        }
    }
}

__global__ void __launch_bounds__(256, 1)
mma_gemm_qkv(const float* __restrict__ bias)
{
    mma_gemm_body<true>(g_x_hi, g_x_lo, g_Wq_hi, g_Wq_lo, bias, nullptr, QKVC);
}

__global__ void __launch_bounds__(256, 1)
mma_gemm_proj(const float* __restrict__ bias, float* __restrict__ out)
{
    mma_gemm_body<false>(g_c_hi, g_c_lo, g_Wp_hi, g_Wp_lo, bias, out, CDIM);
}

// ---------------- HMMA flash attention: BQ=128, BK=64, d=64, 8 warps ----------------
// 4-stage pipeline, one __syncthreads per K-block, base-2 softmax.
constexpr int FA_RS    = 144;
constexpr int FA_ARR   = 64 * FA_RS;        // 9216
constexpr int FA_STAGE = 4 * FA_ARR;        // 36864 (Khi|Klo|Vhi|Vlo)
constexpr int FA_NST   = 4;
constexpr int FA_MASK  = FA_NST * FA_STAGE; // 147456
constexpr int FA_SMEM  = FA_MASK + FA_NST * 256; // 148480
constexpr int FA_NBLK  = NTOK / 64;         // 32
// 0.125 * log2(e)
constexpr float FA_SCL = 0.18033688f;

__device__ __forceinline__ void fa_load_stage(uint32_t su, int tid,
                                              const __nv_bfloat16* Khi,
                                              const __nv_bfloat16* Klo,
                                              const __nv_bfloat16* Vhi,
                                              const __nv_bfloat16* Vlo,
                                              const int* msrc, int blk)
{
    const uint32_t sb = su + (uint32_t)(blk & (FA_NST - 1)) * FA_STAGE;
    const size_t off = (size_t)blk * 64 * 64;
    const __nv_bfloat16* srcs[4] = { Khi + off, Klo + off, Vhi + off, Vlo + off };
#pragma unroll
    for (int i = 0; i < 8; i++) {
        int g = i * 256 + tid;
        int arr = g >> 9;
        int e = g & 511;
        int r = e >> 3;
        int ch = e & 7;
        cp_async16(sb + arr * FA_ARR + r * FA_RS + ch * 16,
                   srcs[arr] + (size_t)r * 64 + ch * 8);
    }
    if (tid < 16)
        cp_async16(su + FA_MASK + (uint32_t)(blk & (FA_NST - 1)) * 256 + tid * 16,
                   msrc + blk * 64 + tid * 4);
    asm volatile("cp.async.commit_group;");
}

__global__ void __launch_bounds__(256)
flash_mma_kernel(const int* __restrict__ mask)
{
    extern __shared__ char smem[];
    const uint32_t su = smem_u32(smem);
    const int tid = threadIdx.x;
    const int wid = tid >> 5, lane = tid & 31;
    const int b = blockIdx.z, h = blockIdx.y;
    const int q0 = blockIdx.x * 128;
    const size_t bh = (size_t)(b * HEADS + h);

    const __nv_bfloat16* Qhi = g_q_hi + (bh * NTOK + q0) * 64;
    const __nv_bfloat16* Qlo = g_q_lo + (bh * NTOK + q0) * 64;
    const __nv_bfloat16* Khi = g_k_hi + bh * NTOK * 64;
    const __nv_bfloat16* Klo = g_k_lo + bh * NTOK * 64;
    const __nv_bfloat16* Vhi = g_v_hi + bh * NTOK * 64;
    const __nv_bfloat16* Vlo = g_v_lo + bh * NTOK * 64;
    const int* msrc = mask + b * NTOK;

    // ---- stage Q into smem (stage-0 region), pull to registers, then free it ----
#pragma unroll
    for (int i = 0; i < 8; i++) {
        int g = i * 256 + tid;
        int arr = g >> 10;
        int e = g & 1023;
        int r = e >> 3;
        int ch = e & 7;
        cp_async16(su + arr * 18432 + r * FA_RS + ch * 16,
                   (arr ? Qlo : Qhi) + (size_t)r * 64 + ch * 8);
    }
    asm volatile("cp.async.commit_group;");
    asm volatile("cp.async.wait_group 0;" ::: "memory");
    __syncthreads();

    uint32_t qh[4][4], ql[4][4];
    {
        const int ar = wid * 16 + (lane & 15);
        const uint32_t ab = (uint32_t)((lane >> 4) << 4);
#pragma unroll
        for (int ks = 0; ks < 4; ks++) {
            uint32_t base = (uint32_t)(ar * FA_RS) + ab + ks * 32;
            ldsm_x4(qh[ks][0], qh[ks][1], qh[ks][2], qh[ks][3], su + base);
            ldsm_x4(ql[ks][0], ql[ks][1], ql[ks][2], ql[ks][3], su + 18432 + base);
        }
    }
    __syncthreads();

    float O[8][4];
#pragma unroll
    for (int t = 0; t < 8; t++)
#pragma unroll
        for (int f = 0; f < 4; f++) O[t][f] = 0.f;
    float m0 = -1e30f, m1 = -1e30f, l0 = 0.f, l1 = 0.f;

    fa_load_stage(su, tid, Khi, Klo, Vhi, Vlo, msrc, 0);
    fa_load_stage(su, tid, Khi, Klo, Vhi, Vlo, msrc, 1);
    fa_load_stage(su, tid, Khi, Klo, Vhi, Vlo, msrc, 2);

    const int kb_row = (lane & 7) | ((lane & 16) >> 1);
    const uint32_t kb_off = (uint32_t)((lane & 8) << 1);
    const int v_row = lane & 15;
    const uint32_t v_off = (uint32_t)(((lane & 16) >> 4) * 16);

    for (int blk = 0; blk < FA_NBLK; blk++) {
        if (blk < FA_NBLK - 2)       asm volatile("cp.async.wait_group 2;" ::: "memory");
        else if (blk == FA_NBLK - 2) asm volatile("cp.async.wait_group 1;" ::: "memory");
        else                         asm volatile("cp.async.wait_group 0;" ::: "memory");
        __syncthreads();
        if (blk + 3 < FA_NBLK) fa_load_stage(su, tid, Khi, Klo, Vhi, Vlo, msrc, blk + 3);

        const uint32_t sb = su + (uint32_t)(blk & (FA_NST - 1)) * FA_STAGE;

        // ---- S = Q K^T (3-term split) ----
        float S[8][4];
#pragma unroll
        for (int t = 0; t < 8; t++)
#pragma unroll
            for (int f = 0; f < 4; f++) S[t][f] = 0.f;

#pragma unroll
        for (int ks = 0; ks < 4; ks++) {
            uint32_t kh[4][4], kl[4][4];
#pragma unroll
            for (int np = 0; np < 4; np++) {
                uint32_t base = (uint32_t)((np * 16 + kb_row) * FA_RS) + kb_off + ks * 32;
                ldsm_x4(kh[np][0], kh[np][1], kh[np][2], kh[np][3], sb + 0 * FA_ARR + base);
                ldsm_x4(kl[np][0], kl[np][1], kl[np][2], kl[np][3], sb + 1 * FA_ARR + base);
            }
#pragma unroll
            for (int np = 0; np < 4; np++) {
                mma_bf16(S[2 * np],     qh[ks], &kh[np][0]);
                mma_bf16(S[2 * np + 1], qh[ks], &kh[np][2]);
            }
#pragma unroll
            for (int np = 0; np < 4; np++) {
                mma_bf16(S[2 * np],     ql[ks], &kh[np][0]);
                mma_bf16(S[2 * np + 1], ql[ks], &kh[np][2]);
            }
#pragma unroll
            for (int np = 0; np < 4; np++) {
                mma_bf16(S[2 * np],     qh[ks], &kl[np][0]);
                mma_bf16(S[2 * np + 1], qh[ks], &kl[np][2]);
            }
        }

        // ---- mask + online softmax (base-2 logits) ----
        const int* mrow = reinterpret_cast<const int*>(smem + FA_MASK + (blk & (FA_NST - 1)) * 256);
        float mx0 = -1e30f, mx1 = -1e30f;
#pragma unroll
        for (int t = 0; t < 8; t++) {
            int c0 = t * 8 + (lane & 3) * 2;
            float k0m = (mrow[c0] == 0) ? -1e30f : 0.f;
            float k1m = (mrow[c0 + 1] == 0) ? -1e30f : 0.f;
            S[t][0] = S[t][0] * FA_SCL + k0m;
            S[t][1] = S[t][1] * FA_SCL + k1m;
            S[t][2] = S[t][2] * FA_SCL + k0m;
            S[t][3] = S[t][3] * FA_SCL + k1m;
            mx0 = fmaxf(mx0, fmaxf(S[t][0], S[t][1]));
            mx1 = fmaxf(mx1, fmaxf(S[t][2], S[t][3]));
        }
#pragma unroll
        for (int off = 1; off <= 2; off <<= 1) {
            mx0 = fmaxf(mx0, __shfl_xor_sync(0xffffffffu, mx0, off));
            mx1 = fmaxf(mx1, __shfl_xor_sync(0xffffffffu, mx1, off));
        }
        float mn0 = fmaxf(m0, mx0), mn1 = fmaxf(m1, mx1);
        float al0 = ex2(m0 - mn0), al1 = ex2(m1 - mn1);
        m0 = mn0; m1 = mn1;
        float s0 = 0.f, s1 = 0.f;
#pragma unroll
        for (int t = 0; t < 8; t++) {
            S[t][0] = ex2(S[t][0] - mn0);
            S[t][1] = ex2(S[t][1] - mn0);
            S[t][2] = ex2(S[t][2] - mn1);
            S[t][3] = ex2(S[t][3] - mn1);
            s0 += S[t][0] + S[t][1];
            s1 += S[t][2] + S[t][3];
        }
#pragma unroll
        for (int off = 1; off <= 2; off <<= 1) {
            s0 += __shfl_xor_sync(0xffffffffu, s0, off);
            s1 += __shfl_xor_sync(0xffffffffu, s1, off);
        }
        l0 = l0 * al0 + s0;
        l1 = l1 * al1 + s1;
#pragma unroll
        for (int t = 0; t < 8; t++) {
            O[t][0] *= al0; O[t][1] *= al0;
            O[t][2] *= al1; O[t][3] *= al1;
        }

        // ---- pack P into hi/lo A-fragments ----
        uint32_t ph[4][4], pl[4][4];
#pragma unroll
        for (int s = 0; s < 4; s++) {
#pragma unroll
            for (int half = 0; half < 2; half++) {
#pragma unroll
                for (int rr = 0; rr < 2; rr++) {
                    float p0 = S[2 * s + half][rr * 2 + 0];
                    float p1 = S[2 * s + half][rr * 2 + 1];
                    __nv_bfloat16 h0, lo0, h1, lo1;
                    split2(p0, h0, lo0);
                    split2(p1, h1, lo1);
                    int ri = half * 2 + rr;
                    __nv_bfloat162 vh(h0, h1), vl(lo0, lo1);
                    ph[s][ri] = *reinterpret_cast<uint32_t*>(&vh);
                    pl[s][ri] = *reinterpret_cast<uint32_t*>(&vl);
                }
            }
        }

        // ---- O += P V (3-term split) ----
#pragma unroll
        for (int s = 0; s < 4; s++) {
            uint32_t vh[4][4], vl[4][4];
#pragma unroll
            for (int np = 0; np < 4; np++) {
                uint32_t base = (uint32_t)((16 * s + v_row) * FA_RS) + np * 32 + v_off;
                ldsm_x4_t(vh[np][0], vh[np][1], vh[np][2], vh[np][3], sb + 2 * FA_ARR + base);
                ldsm_x4_t(vl[np][0], vl[np][1], vl[np][2], vl[np][3], sb + 3 * FA_ARR + base);
            }
#pragma unroll
            for (int np = 0; np < 4; np++) {
                mma_bf16(O[2 * np],     ph[s], &vh[np][0]);
                mma_bf16(O[2 * np + 1], ph[s], &vh[np][2]);
            }
#pragma unroll
            for (int np = 0; np < 4; np++) {
                mma_bf16(O[2 * np],     pl[s], &vh[np][0]);
                mma_bf16(O[2 * np + 1], pl[s], &vh[np][2]);
            }
#pragma unroll
            for (int np = 0; np < 4; np++) {
                mma_bf16(O[2 * np],     ph[s], &vl[np][0]);
                mma_bf16(O[2 * np + 1], ph[s], &vl[np][2]);
            }
        }
    }

    // ---- normalize, split, write ctx [B][N][C] hi/lo ----
    const float inv0 = 1.0f / l0, inv1 = 1.0f / l1;
    const int r0 = q0 + wid * 16 + (lane >> 2);
    __nv_bfloat162* chi = reinterpret_cast<__nv_bfloat162*>(g_c_hi);
    __nv_bfloat162* clo = reinterpret_cast<__nv_bfloat162*>(g_c_lo);
#pragma unroll
    for (int t = 0; t < 8; t++) {
        int d = t * 8 + (lane & 3) * 2;
        size_t di0 = (((size_t)(b * NTOK + r0) * CDIM) + h * 64 + d) >> 1;
        size_t di1 = (((size_t)(b * NTOK + r0 + 8) * CDIM) + h * 64 + d) >> 1;
        float v0 = O[t][0] * inv0, v1 = O[t][1] * inv0;
        float v2 = O[t][2] * inv1, v3 = O[t][3] * inv1;
        __nv_bfloat16 h0, lo0, h1, lo1;
        split2(v0, h0, lo0); split2(v1, h1, lo1);
        chi[di0] = __nv_bfloat162(h0, h1);
        clo[di0] = __nv_bfloat162(lo0, lo1);
        split2(v2, h0, lo0); split2(v3, h1, lo1);
        chi[di1] = __nv_bfloat162(h0, h1);
        clo[di1] = __nv_bfloat162(lo0, lo1);
    }
}

// ---------------- launch ----------------
extern "C" void kernel_launch(void* const* d_in, const int* in_sizes, int n_in,
                              void* d_out, int out_size)
{
    (void)in_sizes; (void)n_in; (void)out_size;
    const float* x    = (const float*)d_in[0];
    const int*   mask = (const int*)d_in[1];
    const float* Wqkv = (const float*)d_in[2];
    const float* bqkv = (const float*)d_in[3];
    const float* Aqkv = (const float*)d_in[4];
    const float* Bqkv = (const float*)d_in[5];
    const float* Wp   = (const float*)d_in[6];
    const float* bp   = (const float*)d_in[7];
    const float* Ap   = (const float*)d_in[8];
    const float* Bp   = (const float*)d_in[9];
    float* out = (float*)d_out;

    fuse_qkv_kernel<<<(QKVC * CDIM + 255) / 256, 256>>>(Wqkv, Bqkv, Aqkv);
    fuse_p_kernel<<<(CDIM * CDIM + 255) / 256, 256>>>(Wp, Bp, Ap);
    cvt_x_kernel<<<(MROWS * CDIM + 255) / 256, 256>>>(x);

    cudaFuncSetAttribute(mma_gemm_qkv, cudaFuncAttributeMaxDynamicSharedMemorySize, GM_SMEM);
    mma_gemm_qkv<<<dim3(QKVC / 128, MROWS / 128), 256, GM_SMEM>>>(bqkv);

    cudaFuncSetAttribute(flash_mma_kernel, cudaFuncAttributeMaxDynamicSharedMemorySize, FA_SMEM);
    flash_mma_kernel<<<dim3(NTOK / 128, HEADS, BATCH), 256, FA_SMEM>>>(mask);

    cudaFuncSetAttribute(mma_gemm_proj, cudaFuncAttributeMaxDynamicSharedMemorySize, GM_SMEM);
    mma_gemm_proj<<<dim3(CDIM / 128, MROWS / 128), 256, GM_SMEM>>>(bp, out);
}

// round 9
// speedup vs baseline: 1.0512x; 1.0512x over previous
#include <cuda_runtime.h>
#include <cuda_bf16.h>
#include <cstdint>

// ---------------- problem constants ----------------
constexpr int BATCH = 2;
constexpr int NTOK  = 2048;
constexpr int CDIM  = 1024;
constexpr int HEADS = 16;
constexpr int HDIM  = 64;
constexpr int MROWS = BATCH * NTOK;     // 4096
constexpr int QKVC  = 3 * CDIM;         // 3072

// ---------------- scratch (device globals, no allocation) ----------------
__device__ __nv_bfloat16 g_x_hi[MROWS * CDIM];
__device__ __nv_bfloat16 g_x_lo[MROWS * CDIM];
__device__ __nv_bfloat16 g_Wq_hi[QKVC * CDIM];
__device__ __nv_bfloat16 g_Wq_lo[QKVC * CDIM];
__device__ __nv_bfloat16 g_Wp_hi[CDIM * CDIM];
__device__ __nv_bfloat16 g_Wp_lo[CDIM * CDIM];
__device__ __nv_bfloat16 g_q_hi[MROWS * CDIM];
__device__ __nv_bfloat16 g_q_lo[MROWS * CDIM];
__device__ __nv_bfloat16 g_k_hi[MROWS * CDIM];
__device__ __nv_bfloat16 g_k_lo[MROWS * CDIM];
__device__ __nv_bfloat16 g_v_hi[MROWS * CDIM];
__device__ __nv_bfloat16 g_v_lo[MROWS * CDIM];
__device__ __nv_bfloat16 g_c_hi[MROWS * CDIM];
__device__ __nv_bfloat16 g_c_lo[MROWS * CDIM];

// ---------------- helpers ----------------
__device__ __forceinline__ void split2(float v, __nv_bfloat16& h, __nv_bfloat16& l)
{
    h = __float2bfloat16_rn(v);
    l = __float2bfloat16_rn(v - __bfloat162float(h));
}

__device__ __forceinline__ uint32_t smem_u32(const void* p)
{
    uint32_t a;
    asm("{ .reg .u64 t; cvta.to.shared.u64 t, %1; cvt.u32.u64 %0, t; }" : "=r"(a) : "l"(p));
    return a;
}

__device__ __forceinline__ void cp_async16(uint32_t dst, const void* src)
{
    asm volatile("cp.async.cg.shared.global [%0], [%1], 16;" :: "r"(dst), "l"(src));
}

__device__ __forceinline__ void ldsm_x4(uint32_t& r0, uint32_t& r1, uint32_t& r2, uint32_t& r3,
                                        uint32_t addr)
{
    asm volatile("ldmatrix.sync.aligned.m8n8.x4.shared.b16 {%0,%1,%2,%3}, [%4];"
                 : "=r"(r0), "=r"(r1), "=r"(r2), "=r"(r3) : "r"(addr));
}

__device__ __forceinline__ void ldsm_x4_t(uint32_t& r0, uint32_t& r1, uint32_t& r2, uint32_t& r3,
                                          uint32_t addr)
{
    asm volatile("ldmatrix.sync.aligned.m8n8.x4.trans.shared.b16 {%0,%1,%2,%3}, [%4];"
                 : "=r"(r0), "=r"(r1), "=r"(r2), "=r"(r3) : "r"(addr));
}

__device__ __forceinline__ void mma_bf16(float* c, const uint32_t* a, const uint32_t* b)
{
    asm volatile("mma.sync.aligned.m16n8k16.row.col.f32.bf16.bf16.f32 "
                 "{%0,%1,%2,%3}, {%4,%5,%6,%7}, {%8,%9}, {%0,%1,%2,%3};"
                 : "+f"(c[0]), "+f"(c[1]), "+f"(c[2]), "+f"(c[3])
                 : "r"(a[0]), "r"(a[1]), "r"(a[2]), "r"(a[3]), "r"(b[0]), "r"(b[1]));
}

__device__ __forceinline__ float ex2(float x)
{
    float r;
    asm("ex2.approx.ftz.f32 %0, %1;" : "=f"(r) : "f"(x));
    return r;
}

// ---------------- conversion kernel ----------------
__global__ void cvt_x_kernel(const float* __restrict__ x)
{
    int i = blockIdx.x * blockDim.x + threadIdx.x;
    if (i < MROWS * CDIM) split2(x[i], g_x_hi[i], g_x_lo[i]);
}

// ---------------- weight fusion + split: Weff = W + 2 * B @ A ----------------
__device__ __forceinline__ void fuse_body(const float* __restrict__ W,
                                          const float* __restrict__ Bm,
                                          const float* __restrict__ A,
                                          __nv_bfloat16* __restrict__ Whi,
                                          __nv_bfloat16* __restrict__ Wlo, int total)
{
    int idx = blockIdx.x * blockDim.x + threadIdx.x;
    if (idx >= total) return;
    int i = idx >> 10;
    int j = idx & 1023;
    float s = 0.f;
#pragma unroll
    for (int r = 0; r < 16; r++) s += Bm[i * 16 + r] * A[r * CDIM + j];
    split2(W[idx] + 2.0f * s, Whi[idx], Wlo[idx]);
}

__global__ void fuse_qkv_kernel(const float* __restrict__ W, const float* __restrict__ Bm,
                                const float* __restrict__ A)
{
    fuse_body(W, Bm, A, g_Wq_hi, g_Wq_lo, QKVC * CDIM);
}

__global__ void fuse_p_kernel(const float* __restrict__ W, const float* __restrict__ Bm,
                              const float* __restrict__ A)
{
    fuse_body(W, Bm, A, g_Wp_hi, g_Wp_lo, CDIM * CDIM);
}

// ---------------- HMMA GEMM (128x128 tile, 8 warps, 3-term split bf16) --------------
// 2-stage pipeline + 128-reg cap -> 2 CTAs/SM (reg file: 2*256*128 = 64K exactly).
constexpr int GM_RS    = 80;
constexpr int GM_ARR   = 128 * GM_RS;        // 10240
constexpr int GM_STAGE = 4 * GM_ARR;         // 40960
constexpr int GM_SMEM  = 2 * GM_STAGE;       // 81920 (x2 CTAs = 163840 <= 228KB)
constexpr int KCH      = 32;
constexpr int NCHUNK   = 1024 / KCH;         // 32

__device__ __forceinline__ void gm_load_chunk(uint32_t su, int tid,
                                              const __nv_bfloat16* const* srcs, int c)
{
    uint32_t stage = su + (uint32_t)(c & 1) * GM_STAGE;
    int k0 = c * KCH;
#pragma unroll
    for (int i = 0; i < 8; i++) {
        int g = i * 256 + tid;
        int t = g >> 9;
        int e = g & 511;
        int r = e >> 2;
        int c16 = e & 3;
        cp_async16(stage + t * GM_ARR + r * GM_RS + c16 * 16,
                   srcs[t] + (size_t)r * 1024 + k0 + c16 * 8);
    }
    asm volatile("cp.async.commit_group;");
}

template <bool QKV_SPLIT_OUT>
__device__ __forceinline__ void mma_gemm_body(const __nv_bfloat16* __restrict__ Ahi,
                                              const __nv_bfloat16* __restrict__ Alo,
                                              const __nv_bfloat16* __restrict__ Bhi,
                                              const __nv_bfloat16* __restrict__ Blo,
                                              const float* __restrict__ bias,
                                              float* __restrict__ C, int Nc)
{
    extern __shared__ char smem[];
    const uint32_t su = smem_u32(smem);
    const int tid = threadIdx.x;
    const int wid = tid >> 5, lane = tid & 31;
    const int warp_m = wid >> 2, warp_n = wid & 3;
    const int row0 = blockIdx.y * 128;
    const int col0 = blockIdx.x * 128;

    const __nv_bfloat16* srcs[4] = {
        Ahi + (size_t)row0 * 1024, Alo + (size_t)row0 * 1024,
        Bhi + (size_t)col0 * 1024, Blo + (size_t)col0 * 1024 };

    float acc[4][4][4];
#pragma unroll
    for (int mt = 0; mt < 4; mt++)
#pragma unroll
        for (int nt = 0; nt < 4; nt++)
#pragma unroll
            for (int f = 0; f < 4; f++) acc[mt][nt][f] = 0.f;

    gm_load_chunk(su, tid, srcs, 0);

    const int a_row = warp_m * 64 + (lane & 15);
    const int a_kb  = (lane >> 4) << 4;
    const int b_row = warp_n * 32 + ((lane & 7) | ((lane & 16) >> 1));
    const int b_kb  = (lane & 8) << 1;

    for (int c = 0; c < NCHUNK; c++) {
        if (c + 1 < NCHUNK) {
            __syncthreads();
            gm_load_chunk(su, tid, srcs, c + 1);
            asm volatile("cp.async.wait_group 1;" ::: "memory");
        } else {
            asm volatile("cp.async.wait_group 0;" ::: "memory");
        }
        __syncthreads();

        const uint32_t stage = su + (uint32_t)(c & 1) * GM_STAGE;
#pragma unroll
        for (int ks = 0; ks < 2; ks++) {
            const uint32_t koff = ks * 32;

            uint32_t ah[4][4], al[4][4];
#pragma unroll
            for (int mt = 0; mt < 4; mt++) {
                uint32_t base = (uint32_t)((a_row + mt * 16) * GM_RS + a_kb + koff);
                ldsm_x4(ah[mt][0], ah[mt][1], ah[mt][2], ah[mt][3], stage + 0 * GM_ARR + base);
                ldsm_x4(al[mt][0], al[mt][1], al[mt][2], al[mt][3], stage + 1 * GM_ARR + base);
            }
            uint32_t bh[4][2], bl[4][2];
#pragma unroll
            for (int np = 0; np < 2; np++) {
                uint32_t base = (uint32_t)((b_row + np * 16) * GM_RS + b_kb + koff);
                uint32_t r0, r1, r2, r3;
                ldsm_x4(r0, r1, r2, r3, stage + 2 * GM_ARR + base);
                bh[np * 2][0] = r0; bh[np * 2][1] = r1;
                bh[np * 2 + 1][0] = r2; bh[np * 2 + 1][1] = r3;
                ldsm_x4(r0, r1, r2, r3, stage + 3 * GM_ARR + base);
                bl[np * 2][0] = r0; bl[np * 2][1] = r1;
                bl[np * 2 + 1][0] = r2; bl[np * 2 + 1][1] = r3;
            }
#pragma unroll
            for (int mt = 0; mt < 4; mt++)
#pragma unroll
                for (int nt = 0; nt < 4; nt++) {
                    mma_bf16(acc[mt][nt], ah[mt], bh[nt]);
                    mma_bf16(acc[mt][nt], al[mt], bh[nt]);
                    mma_bf16(acc[mt][nt], ah[mt], bl[nt]);
                }
        }
    }

    if (!QKV_SPLIT_OUT) {
#pragma unroll
        for (int mt = 0; mt < 4; mt++) {
            int rg = row0 + warp_m * 64 + mt * 16 + (lane >> 2);
#pragma unroll
            for (int nt = 0; nt < 4; nt++) {
                int cg = col0 + warp_n * 32 + nt * 8 + (lane & 3) * 2;
                float b0 = bias[cg], b1 = bias[cg + 1];
                float2 v0 = make_float2(acc[mt][nt][0] + b0, acc[mt][nt][1] + b1);
                float2 v1 = make_float2(acc[mt][nt][2] + b0, acc[mt][nt][3] + b1);
                *reinterpret_cast<float2*>(&C[(size_t)rg * Nc + cg]) = v0;
                *reinterpret_cast<float2*>(&C[(size_t)(rg + 8) * Nc + cg]) = v1;
            }
        }
    } else {
        __nv_bfloat162* hiA[3] = { reinterpret_cast<__nv_bfloat162*>(g_q_hi),
                                   reinterpret_cast<__nv_bfloat162*>(g_k_hi),
                                   reinterpret_cast<__nv_bfloat162*>(g_v_hi) };
        __nv_bfloat162* loA[3] = { reinterpret_cast<__nv_bfloat162*>(g_q_lo),
                                   reinterpret_cast<__nv_bfloat162*>(g_k_lo),
                                   reinterpret_cast<__nv_bfloat162*>(g_v_lo) };
#pragma unroll
        for (int nt = 0; nt < 4; nt++) {
            int cg = col0 + warp_n * 32 + nt * 8 + (lane & 3) * 2;
            int which = cg >> 10;
            int rem = cg & 1023;
            int h = rem >> 6;
            int d = rem & 63;
            float b0 = bias[cg], b1 = bias[cg + 1];
#pragma unroll
            for (int mt = 0; mt < 4; mt++) {
                int rbase = row0 + warp_m * 64 + mt * 16 + (lane >> 2);
#pragma unroll
                for (int half = 0; half < 2; half++) {
                    int r = rbase + half * 8;
                    int bb = r >> 11, n = r & 2047;
                    size_t di = (((size_t)((bb << 4) + h) * 2048 + n) * 64 + d) >> 1;
                    float v0 = acc[mt][nt][half * 2 + 0] + b0;
                    float v1 = acc[mt][nt][half * 2 + 1] + b1;
                    __nv_bfloat16 h0, l0, h1, l1;
                    split2(v0, h0, l0);
                    split2(v1, h1, l1);
                    hiA[which][di] = __nv_bfloat162(h0, h1);
                    loA[which][di] = __nv_bfloat162(l0, l1);
                }
            }
        }
    }
}

__global__ void __launch_bounds__(256, 2)
mma_gemm_qkv(const float* __restrict__ bias)
{
    mma_gemm_body<true>(g_x_hi, g_x_lo, g_Wq_hi, g_Wq_lo, bias, nullptr, QKVC);
}

__global__ void __launch_bounds__(256, 2)
mma_gemm_proj(const float* __restrict__ bias, float* __restrict__ out)
{
    mma_gemm_body<false>(g_c_hi, g_c_lo, g_Wp_hi, g_Wp_lo, bias, out, CDIM);
}

// ---------------- HMMA flash attention: BQ=128, BK=64, d=64, 8 warps ----------------
// 4-stage pipeline, one __syncthreads per K-block, base-2 softmax. (unchanged R8)
constexpr int FA_RS    = 144;
constexpr int FA_ARR   = 64 * FA_RS;        // 9216
constexpr int FA_STAGE = 4 * FA_ARR;        // 36864 (Khi|Klo|Vhi|Vlo)
constexpr int FA_NST   = 4;
constexpr int FA_MASK  = FA_NST * FA_STAGE; // 147456
constexpr int FA_SMEM  = FA_MASK + FA_NST * 256; // 148480
constexpr int FA_NBLK  = NTOK / 64;         // 32
constexpr float FA_SCL = 0.18033688f;       // 0.125 * log2(e)

__device__ __forceinline__ void fa_load_stage(uint32_t su, int tid,
                                              const __nv_bfloat16* Khi,
                                              const __nv_bfloat16* Klo,
                                              const __nv_bfloat16* Vhi,
                                              const __nv_bfloat16* Vlo,
                                              const int* msrc, int blk)
{
    const uint32_t sb = su + (uint32_t)(blk & (FA_NST - 1)) * FA_STAGE;
    const size_t off = (size_t)blk * 64 * 64;
    const __nv_bfloat16* srcs[4] = { Khi + off, Klo + off, Vhi + off, Vlo + off };
#pragma unroll
    for (int i = 0; i < 8; i++) {
        int g = i * 256 + tid;
        int arr = g >> 9;
        int e = g & 511;
        int r = e >> 3;
        int ch = e & 7;
        cp_async16(sb + arr * FA_ARR + r * FA_RS + ch * 16,
                   srcs[arr] + (size_t)r * 64 + ch * 8);
    }
    if (tid < 16)
        cp_async16(su + FA_MASK + (uint32_t)(blk & (FA_NST - 1)) * 256 + tid * 16,
                   msrc + blk * 64 + tid * 4);
    asm volatile("cp.async.commit_group;");
}

__global__ void __launch_bounds__(256)
flash_mma_kernel(const int* __restrict__ mask)
{
    extern __shared__ char smem[];
    const uint32_t su = smem_u32(smem);
    const int tid = threadIdx.x;
    const int wid = tid >> 5, lane = tid & 31;
    const int b = blockIdx.z, h = blockIdx.y;
    const int q0 = blockIdx.x * 128;
    const size_t bh = (size_t)(b * HEADS + h);

    const __nv_bfloat16* Qhi = g_q_hi + (bh * NTOK + q0) * 64;
    const __nv_bfloat16* Qlo = g_q_lo + (bh * NTOK + q0) * 64;
    const __nv_bfloat16* Khi = g_k_hi + bh * NTOK * 64;
    const __nv_bfloat16* Klo = g_k_lo + bh * NTOK * 64;
    const __nv_bfloat16* Vhi = g_v_hi + bh * NTOK * 64;
    const __nv_bfloat16* Vlo = g_v_lo + bh * NTOK * 64;
    const int* msrc = mask + b * NTOK;

#pragma unroll
    for (int i = 0; i < 8; i++) {
        int g = i * 256 + tid;
        int arr = g >> 10;
        int e = g & 1023;
        int r = e >> 3;
        int ch = e & 7;
        cp_async16(su + arr * 18432 + r * FA_RS + ch * 16,
                   (arr ? Qlo : Qhi) + (size_t)r * 64 + ch * 8);
    }
    asm volatile("cp.async.commit_group;");
    asm volatile("cp.async.wait_group 0;" ::: "memory");
    __syncthreads();

    uint32_t qh[4][4], ql[4][4];
    {
        const int ar = wid * 16 + (lane & 15);
        const uint32_t ab = (uint32_t)((lane >> 4) << 4);
#pragma unroll
        for (int ks = 0; ks < 4; ks++) {
            uint32_t base = (uint32_t)(ar * FA_RS) + ab + ks * 32;
            ldsm_x4(qh[ks][0], qh[ks][1], qh[ks][2], qh[ks][3], su + base);
            ldsm_x4(ql[ks][0], ql[ks][1], ql[ks][2], ql[ks][3], su + 18432 + base);
        }
    }
    __syncthreads();

    float O[8][4];
#pragma unroll
    for (int t = 0; t < 8; t++)
#pragma unroll
        for (int f = 0; f < 4; f++) O[t][f] = 0.f;
    float m0 = -1e30f, m1 = -1e30f, l0 = 0.f, l1 = 0.f;

    fa_load_stage(su, tid, Khi, Klo, Vhi, Vlo, msrc, 0);
    fa_load_stage(su, tid, Khi, Klo, Vhi, Vlo, msrc, 1);
    fa_load_stage(su, tid, Khi, Klo, Vhi, Vlo, msrc, 2);

    const int kb_row = (lane & 7) | ((lane & 16) >> 1);
    const uint32_t kb_off = (uint32_t)((lane & 8) << 1);
    const int v_row = lane & 15;
    const uint32_t v_off = (uint32_t)(((lane & 16) >> 4) * 16);

    for (int blk = 0; blk < FA_NBLK; blk++) {
        if (blk < FA_NBLK - 2)       asm volatile("cp.async.wait_group 2;" ::: "memory");
        else if (blk == FA_NBLK - 2) asm volatile("cp.async.wait_group 1;" ::: "memory");
        else                         asm volatile("cp.async.wait_group 0;" ::: "memory");
        __syncthreads();
        if (blk + 3 < FA_NBLK) fa_load_stage(su, tid, Khi, Klo, Vhi, Vlo, msrc, blk + 3);

        const uint32_t sb = su + (uint32_t)(blk & (FA_NST - 1)) * FA_STAGE;

        float S[8][4];
#pragma unroll
        for (int t = 0; t < 8; t++)
#pragma unroll
            for (int f = 0; f < 4; f++) S[t][f] = 0.f;

#pragma unroll
        for (int ks = 0; ks < 4; ks++) {
            uint32_t kh[4][4], kl[4][4];
#pragma unroll
            for (int np = 0; np < 4; np++) {
                uint32_t base = (uint32_t)((np * 16 + kb_row) * FA_RS) + kb_off + ks * 32;
                ldsm_x4(kh[np][0], kh[np][1], kh[np][2], kh[np][3], sb + 0 * FA_ARR + base);
                ldsm_x4(kl[np][0], kl[np][1], kl[np][2], kl[np][3], sb + 1 * FA_ARR + base);
            }
#pragma unroll
            for (int np = 0; np < 4; np++) {
                mma_bf16(S[2 * np],     qh[ks], &kh[np][0]);
                mma_bf16(S[2 * np + 1], qh[ks], &kh[np][2]);
            }
#pragma unroll
            for (int np = 0; np < 4; np++) {
                mma_bf16(S[2 * np],     ql[ks], &kh[np][0]);
                mma_bf16(S[2 * np + 1], ql[ks], &kh[np][2]);
            }
#pragma unroll
            for (int np = 0; np < 4; np++) {
                mma_bf16(S[2 * np],     qh[ks], &kl[np][0]);
                mma_bf16(S[2 * np + 1], qh[ks], &kl[np][2]);
            }
        }

        const int* mrow = reinterpret_cast<const int*>(smem + FA_MASK + (blk & (FA_NST - 1)) * 256);
        float mx0 = -1e30f, mx1 = -1e30f;
#pragma unroll
        for (int t = 0; t < 8; t++) {
            int c0 = t * 8 + (lane & 3) * 2;
            float k0m = (mrow[c0] == 0) ? -1e30f : 0.f;
            float k1m = (mrow[c0 + 1] == 0) ? -1e30f : 0.f;
            S[t][0] = S[t][0] * FA_SCL + k0m;
            S[t][1] = S[t][1] * FA_SCL + k1m;
            S[t][2] = S[t][2] * FA_SCL + k0m;
            S[t][3] = S[t][3] * FA_SCL + k1m;
            mx0 = fmaxf(mx0, fmaxf(S[t][0], S[t][1]));
            mx1 = fmaxf(mx1, fmaxf(S[t][2], S[t][3]));
        }
#pragma unroll
        for (int off = 1; off <= 2; off <<= 1) {
            mx0 = fmaxf(mx0, __shfl_xor_sync(0xffffffffu, mx0, off));
            mx1 = fmaxf(mx1, __shfl_xor_sync(0xffffffffu, mx1, off));
        }
        float mn0 = fmaxf(m0, mx0), mn1 = fmaxf(m1, mx1);
        float al0 = ex2(m0 - mn0), al1 = ex2(m1 - mn1);
        m0 = mn0; m1 = mn1;
        float s0 = 0.f, s1 = 0.f;
#pragma unroll
        for (int t = 0; t < 8; t++) {
            S[t][0] = ex2(S[t][0] - mn0);
            S[t][1] = ex2(S[t][1] - mn0);
            S[t][2] = ex2(S[t][2] - mn1);
            S[t][3] = ex2(S[t][3] - mn1);
            s0 += S[t][0] + S[t][1];
            s1 += S[t][2] + S[t][3];
        }
#pragma unroll
        for (int off = 1; off <= 2; off <<= 1) {
            s0 += __shfl_xor_sync(0xffffffffu, s0, off);
            s1 += __shfl_xor_sync(0xffffffffu, s1, off);
        }
        l0 = l0 * al0 + s0;
        l1 = l1 * al1 + s1;
#pragma unroll
        for (int t = 0; t < 8; t++) {
            O[t][0] *= al0; O[t][1] *= al0;
            O[t][2] *= al1; O[t][3] *= al1;
        }

        uint32_t ph[4][4], pl[4][4];
#pragma unroll
        for (int s = 0; s < 4; s++) {
#pragma unroll
            for (int half = 0; half < 2; half++) {
#pragma unroll
                for (int rr = 0; rr < 2; rr++) {
                    float p0 = S[2 * s + half][rr * 2 + 0];
                    float p1 = S[2 * s + half][rr * 2 + 1];
                    __nv_bfloat16 h0, lo0, h1, lo1;
                    split2(p0, h0, lo0);
                    split2(p1, h1, lo1);
                    int ri = half * 2 + rr;
                    __nv_bfloat162 vh(h0, h1), vl(lo0, lo1);
                    ph[s][ri] = *reinterpret_cast<uint32_t*>(&vh);
                    pl[s][ri] = *reinterpret_cast<uint32_t*>(&vl);
                }
            }
        }

#pragma unroll
        for (int s = 0; s < 4; s++) {
            uint32_t vh[4][4], vl[4][4];
#pragma unroll
            for (int np = 0; np < 4; np++) {
                uint32_t base = (uint32_t)((16 * s + v_row) * FA_RS) + np * 32 + v_off;
                ldsm_x4_t(vh[np][0], vh[np][1], vh[np][2], vh[np][3], sb + 2 * FA_ARR + base);
                ldsm_x4_t(vl[np][0], vl[np][1], vl[np][2], vl[np][3], sb + 3 * FA_ARR + base);
            }
#pragma unroll
            for (int np = 0; np < 4; np++) {
                mma_bf16(O[2 * np],     ph[s], &vh[np][0]);
                mma_bf16(O[2 * np + 1], ph[s], &vh[np][2]);
            }
#pragma unroll
            for (int np = 0; np < 4; np++) {
                mma_bf16(O[2 * np],     pl[s], &vh[np][0]);
                mma_bf16(O[2 * np + 1], pl[s], &vh[np][2]);
            }
#pragma unroll
            for (int np = 0; np < 4; np++) {
                mma_bf16(O[2 * np],     ph[s], &vl[np][0]);
                mma_bf16(O[2 * np + 1], ph[s], &vl[np][2]);
            }
        }
    }

    const float inv0 = 1.0f / l0, inv1 = 1.0f / l1;
    const int r0 = q0 + wid * 16 + (lane >> 2);
    __nv_bfloat162* chi = reinterpret_cast<__nv_bfloat162*>(g_c_hi);
    __nv_bfloat162* clo = reinterpret_cast<__nv_bfloat162*>(g_c_lo);
#pragma unroll
    for (int t = 0; t < 8; t++) {
        int d = t * 8 + (lane & 3) * 2;
        size_t di0 = (((size_t)(b * NTOK + r0) * CDIM) + h * 64 + d) >> 1;
        size_t di1 = (((size_t)(b * NTOK + r0 + 8) * CDIM) + h * 64 + d) >> 1;
        float v0 = O[t][0] * inv0, v1 = O[t][1] * inv0;
        float v2 = O[t][2] * inv1, v3 = O[t][3] * inv1;
        __nv_bfloat16 h0, lo0, h1, lo1;
        split2(v0, h0, lo0); split2(v1, h1, lo1);
        chi[di0] = __nv_bfloat162(h0, h1);
        clo[di0] = __nv_bfloat162(lo0, lo1);
        split2(v2, h0, lo0); split2(v3, h1, lo1);
        chi[di1] = __nv_bfloat162(h0, h1);
        clo[di1] = __nv_bfloat162(lo0, lo1);
    }
}

// ---------------- launch ----------------
extern "C" void kernel_launch(void* const* d_in, const int* in_sizes, int n_in,
                              void* d_out, int out_size)
{
    (void)in_sizes; (void)n_in; (void)out_size;
    const float* x    = (const float*)d_in[0];
    const int*   mask = (const int*)d_in[1];
    const float* Wqkv = (const float*)d_in[2];
    const float* bqkv = (const float*)d_in[3];
    const float* Aqkv = (const float*)d_in[4];
    const float* Bqkv = (const float*)d_in[5];
    const float* Wp   = (const float*)d_in[6];
    const float* bp   = (const float*)d_in[7];
    const float* Ap   = (const float*)d_in[8];
    const float* Bp   = (const float*)d_in[9];
    float* out = (float*)d_out;

    fuse_qkv_kernel<<<(QKVC * CDIM + 255) / 256, 256>>>(Wqkv, Bqkv, Aqkv);
    fuse_p_kernel<<<(CDIM * CDIM + 255) / 256, 256>>>(Wp, Bp, Ap);
    cvt_x_kernel<<<(MROWS * CDIM + 255) / 256, 256>>>(x);

    cudaFuncSetAttribute(mma_gemm_qkv, cudaFuncAttributeMaxDynamicSharedMemorySize, GM_SMEM);
    mma_gemm_qkv<<<dim3(QKVC / 128, MROWS / 128), 256, GM_SMEM>>>(bqkv);

    cudaFuncSetAttribute(flash_mma_kernel, cudaFuncAttributeMaxDynamicSharedMemorySize, FA_SMEM);
    flash_mma_kernel<<<dim3(NTOK / 128, HEADS, BATCH), 256, FA_SMEM>>>(mask);

    cudaFuncSetAttribute(mma_gemm_proj, cudaFuncAttributeMaxDynamicSharedMemorySize, GM_SMEM);
    mma_gemm_proj<<<dim3(CDIM / 128, MROWS / 128), 256, GM_SMEM>>>(bp, out);
}

// round 10
// speedup vs baseline: 1.0526x; 1.0012x over previous
#include <cuda_runtime.h>
#include <cuda_bf16.h>
#include <cstdint>

// ---------------- problem constants ----------------
constexpr int BATCH = 2;
constexpr int NTOK  = 2048;
constexpr int CDIM  = 1024;
constexpr int HEADS = 16;
constexpr int HDIM  = 64;
constexpr int MROWS = BATCH * NTOK;     // 4096
constexpr int QKVC  = 3 * CDIM;         // 3072

// ---------------- scratch (device globals, no allocation) ----------------
__device__ __nv_bfloat16 g_x_hi[MROWS * CDIM];
__device__ __nv_bfloat16 g_x_lo[MROWS * CDIM];
__device__ __nv_bfloat16 g_Wq_hi[QKVC * CDIM];
__device__ __nv_bfloat16 g_Wq_lo[QKVC * CDIM];
__device__ __nv_bfloat16 g_Wp_hi[CDIM * CDIM];
__device__ __nv_bfloat16 g_Wp_lo[CDIM * CDIM];
__device__ __nv_bfloat16 g_q_hi[MROWS * CDIM];
__device__ __nv_bfloat16 g_q_lo[MROWS * CDIM];
__device__ __nv_bfloat16 g_k_hi[MROWS * CDIM];
__device__ __nv_bfloat16 g_k_lo[MROWS * CDIM];
__device__ __nv_bfloat16 g_v_hi[MROWS * CDIM];
__device__ __nv_bfloat16 g_v_lo[MROWS * CDIM];
__device__ __nv_bfloat16 g_c_hi[MROWS * CDIM];
__device__ __nv_bfloat16 g_c_lo[MROWS * CDIM];

// ---------------- helpers ----------------
__device__ __forceinline__ void split2(float v, __nv_bfloat16& h, __nv_bfloat16& l)
{
    h = __float2bfloat16_rn(v);
    l = __float2bfloat16_rn(v - __bfloat162float(h));
}

__device__ __forceinline__ uint32_t smem_u32(const void* p)
{
    uint32_t a;
    asm("{ .reg .u64 t; cvta.to.shared.u64 t, %1; cvt.u32.u64 %0, t; }" : "=r"(a) : "l"(p));
    return a;
}

__device__ __forceinline__ void cp_async16(uint32_t dst, const void* src)
{
    asm volatile("cp.async.cg.shared.global [%0], [%1], 16;" :: "r"(dst), "l"(src));
}

__device__ __forceinline__ void ldsm_x4(uint32_t& r0, uint32_t& r1, uint32_t& r2, uint32_t& r3,
                                        uint32_t addr)
{
    asm volatile("ldmatrix.sync.aligned.m8n8.x4.shared.b16 {%0,%1,%2,%3}, [%4];"
                 : "=r"(r0), "=r"(r1), "=r"(r2), "=r"(r3) : "r"(addr));
}

__device__ __forceinline__ void ldsm_x4_t(uint32_t& r0, uint32_t& r1, uint32_t& r2, uint32_t& r3,
                                          uint32_t addr)
{
    asm volatile("ldmatrix.sync.aligned.m8n8.x4.trans.shared.b16 {%0,%1,%2,%3}, [%4];"
                 : "=r"(r0), "=r"(r1), "=r"(r2), "=r"(r3) : "r"(addr));
}

__device__ __forceinline__ void mma_bf16(float* c, const uint32_t* a, const uint32_t* b)
{
    asm volatile("mma.sync.aligned.m16n8k16.row.col.f32.bf16.bf16.f32 "
                 "{%0,%1,%2,%3}, {%4,%5,%6,%7}, {%8,%9}, {%0,%1,%2,%3};"
                 : "+f"(c[0]), "+f"(c[1]), "+f"(c[2]), "+f"(c[3])
                 : "r"(a[0]), "r"(a[1]), "r"(a[2]), "r"(a[3]), "r"(b[0]), "r"(b[1]));
}

__device__ __forceinline__ float ex2(float x)
{
    float r;
    asm("ex2.approx.ftz.f32 %0, %1;" : "=f"(r) : "f"(x));
    return r;
}

// ---------------- conversion kernel ----------------
__global__ void cvt_x_kernel(const float* __restrict__ x)
{
    int i = blockIdx.x * blockDim.x + threadIdx.x;
    if (i < MROWS * CDIM) split2(x[i], g_x_hi[i], g_x_lo[i]);
}

// ---------------- weight fusion + split: Weff = W + 2 * B @ A ----------------
__device__ __forceinline__ void fuse_body(const float* __restrict__ W,
                                          const float* __restrict__ Bm,
                                          const float* __restrict__ A,
                                          __nv_bfloat16* __restrict__ Whi,
                                          __nv_bfloat16* __restrict__ Wlo, int total)
{
    int idx = blockIdx.x * blockDim.x + threadIdx.x;
    if (idx >= total) return;
    int i = idx >> 10;
    int j = idx & 1023;
    float s = 0.f;
#pragma unroll
    for (int r = 0; r < 16; r++) s += Bm[i * 16 + r] * A[r * CDIM + j];
    split2(W[idx] + 2.0f * s, Whi[idx], Wlo[idx]);
}

__global__ void fuse_qkv_kernel(const float* __restrict__ W, const float* __restrict__ Bm,
                                const float* __restrict__ A)
{
    fuse_body(W, Bm, A, g_Wq_hi, g_Wq_lo, QKVC * CDIM);
}

__global__ void fuse_p_kernel(const float* __restrict__ W, const float* __restrict__ Bm,
                              const float* __restrict__ A)
{
    fuse_body(W, Bm, A, g_Wp_hi, g_Wp_lo, CDIM * CDIM);
}

// ---------------- HMMA GEMM (128x128 tile, 8 warps, 3-term split bf16) --------------
// 2-stage pipeline, 128-reg cap (2 CTAs/SM). Term loop HOISTED outermost so the
// 16 accumulator tiles are touched between any same-acc reuse (breaks HMMA RAW chain).
constexpr int GM_RS    = 80;
constexpr int GM_ARR   = 128 * GM_RS;        // 10240
constexpr int GM_STAGE = 4 * GM_ARR;         // 40960
constexpr int GM_SMEM  = 2 * GM_STAGE;       // 81920 (x2 CTAs = 163840 <= 228KB)
constexpr int KCH      = 32;
constexpr int NCHUNK   = 1024 / KCH;         // 32

__device__ __forceinline__ void gm_load_chunk(uint32_t su, int tid,
                                              const __nv_bfloat16* const* srcs, int c)
{
    uint32_t stage = su + (uint32_t)(c & 1) * GM_STAGE;
    int k0 = c * KCH;
#pragma unroll
    for (int i = 0; i < 8; i++) {
        int g = i * 256 + tid;
        int t = g >> 9;
        int e = g & 511;
        int r = e >> 2;
        int c16 = e & 3;
        cp_async16(stage + t * GM_ARR + r * GM_RS + c16 * 16,
                   srcs[t] + (size_t)r * 1024 + k0 + c16 * 8);
    }
    asm volatile("cp.async.commit_group;");
}

template <bool QKV_SPLIT_OUT>
__device__ __forceinline__ void mma_gemm_body(const __nv_bfloat16* __restrict__ Ahi,
                                              const __nv_bfloat16* __restrict__ Alo,
                                              const __nv_bfloat16* __restrict__ Bhi,
                                              const __nv_bfloat16* __restrict__ Blo,
                                              const float* __restrict__ bias,
                                              float* __restrict__ C, int Nc)
{
    extern __shared__ char smem[];
    const uint32_t su = smem_u32(smem);
    const int tid = threadIdx.x;
    const int wid = tid >> 5, lane = tid & 31;
    const int warp_m = wid >> 2, warp_n = wid & 3;
    const int row0 = blockIdx.y * 128;
    const int col0 = blockIdx.x * 128;

    const __nv_bfloat16* srcs[4] = {
        Ahi + (size_t)row0 * 1024, Alo + (size_t)row0 * 1024,
        Bhi + (size_t)col0 * 1024, Blo + (size_t)col0 * 1024 };

    float acc[4][4][4];
#pragma unroll
    for (int mt = 0; mt < 4; mt++)
#pragma unroll
        for (int nt = 0; nt < 4; nt++)
#pragma unroll
            for (int f = 0; f < 4; f++) acc[mt][nt][f] = 0.f;

    gm_load_chunk(su, tid, srcs, 0);

    const int a_row = warp_m * 64 + (lane & 15);
    const int a_kb  = (lane >> 4) << 4;
    const int b_row = warp_n * 32 + ((lane & 7) | ((lane & 16) >> 1));
    const int b_kb  = (lane & 8) << 1;

    for (int c = 0; c < NCHUNK; c++) {
        if (c + 1 < NCHUNK) {
            __syncthreads();
            gm_load_chunk(su, tid, srcs, c + 1);
            asm volatile("cp.async.wait_group 1;" ::: "memory");
        } else {
            asm volatile("cp.async.wait_group 0;" ::: "memory");
        }
        __syncthreads();

        const uint32_t stage = su + (uint32_t)(c & 1) * GM_STAGE;
#pragma unroll
        for (int ks = 0; ks < 2; ks++) {
            const uint32_t koff = ks * 32;

            uint32_t ah[4][4], al[4][4];
#pragma unroll
            for (int mt = 0; mt < 4; mt++) {
                uint32_t base = (uint32_t)((a_row + mt * 16) * GM_RS + a_kb + koff);
                ldsm_x4(ah[mt][0], ah[mt][1], ah[mt][2], ah[mt][3], stage + 0 * GM_ARR + base);
                ldsm_x4(al[mt][0], al[mt][1], al[mt][2], al[mt][3], stage + 1 * GM_ARR + base);
            }
            uint32_t bh[4][2], bl[4][2];
#pragma unroll
            for (int np = 0; np < 2; np++) {
                uint32_t base = (uint32_t)((b_row + np * 16) * GM_RS + b_kb + koff);
                uint32_t r0, r1, r2, r3;
                ldsm_x4(r0, r1, r2, r3, stage + 2 * GM_ARR + base);
                bh[np * 2][0] = r0; bh[np * 2][1] = r1;
                bh[np * 2 + 1][0] = r2; bh[np * 2 + 1][1] = r3;
                ldsm_x4(r0, r1, r2, r3, stage + 3 * GM_ARR + base);
                bl[np * 2][0] = r0; bl[np * 2][1] = r1;
                bl[np * 2 + 1][0] = r2; bl[np * 2 + 1][1] = r3;
            }
            // term loop OUTERMOST: 16 independent accs between same-acc reuses
#pragma unroll
            for (int term = 0; term < 3; term++)
#pragma unroll
                for (int mt = 0; mt < 4; mt++)
#pragma unroll
                    for (int nt = 0; nt < 4; nt++) {
                        const uint32_t* ap = (term == 1) ? al[mt] : ah[mt];
                        const uint32_t* bp = (term == 2) ? bl[nt] : bh[nt];
                        mma_bf16(acc[mt][nt], ap, bp);
                    }
        }
    }

    if (!QKV_SPLIT_OUT) {
#pragma unroll
        for (int mt = 0; mt < 4; mt++) {
            int rg = row0 + warp_m * 64 + mt * 16 + (lane >> 2);
#pragma unroll
            for (int nt = 0; nt < 4; nt++) {
                int cg = col0 + warp_n * 32 + nt * 8 + (lane & 3) * 2;
                float b0 = bias[cg], b1 = bias[cg + 1];
                float2 v0 = make_float2(acc[mt][nt][0] + b0, acc[mt][nt][1] + b1);
                float2 v1 = make_float2(acc[mt][nt][2] + b0, acc[mt][nt][3] + b1);
                *reinterpret_cast<float2*>(&C[(size_t)rg * Nc + cg]) = v0;
                *reinterpret_cast<float2*>(&C[(size_t)(rg + 8) * Nc + cg]) = v1;
            }
        }
    } else {
        __nv_bfloat162* hiA[3] = { reinterpret_cast<__nv_bfloat162*>(g_q_hi),
                                   reinterpret_cast<__nv_bfloat162*>(g_k_hi),
                                   reinterpret_cast<__nv_bfloat162*>(g_v_hi) };
        __nv_bfloat162* loA[3] = { reinterpret_cast<__nv_bfloat162*>(g_q_lo),
                                   reinterpret_cast<__nv_bfloat162*>(g_k_lo),
                                   reinterpret_cast<__nv_bfloat162*>(g_v_lo) };
#pragma unroll
        for (int nt = 0; nt < 4; nt++) {
            int cg = col0 + warp_n * 32 + nt * 8 + (lane & 3) * 2;
            int which = cg >> 10;
            int rem = cg & 1023;
            int h = rem >> 6;
            int d = rem & 63;
            float b0 = bias[cg], b1 = bias[cg + 1];
#pragma unroll
            for (int mt = 0; mt < 4; mt++) {
                int rbase = row0 + warp_m * 64 + mt * 16 + (lane >> 2);
#pragma unroll
                for (int half = 0; half < 2; half++) {
                    int r = rbase + half * 8;
                    int bb = r >> 11, n = r & 2047;
                    size_t di = (((size_t)((bb << 4) + h) * 2048 + n) * 64 + d) >> 1;
                    float v0 = acc[mt][nt][half * 2 + 0] + b0;
                    float v1 = acc[mt][nt][half * 2 + 1] + b1;
                    __nv_bfloat16 h0, l0, h1, l1;
                    split2(v0, h0, l0);
                    split2(v1, h1, l1);
                    hiA[which][di] = __nv_bfloat162(h0, h1);
                    loA[which][di] = __nv_bfloat162(l0, l1);
                }
            }
        }
    }
}

__global__ void __launch_bounds__(256, 2)
mma_gemm_qkv(const float* __restrict__ bias)
{
    mma_gemm_body<true>(g_x_hi, g_x_lo, g_Wq_hi, g_Wq_lo, bias, nullptr, QKVC);
}

__global__ void __launch_bounds__(256, 2)
mma_gemm_proj(const float* __restrict__ bias, float* __restrict__ out)
{
    mma_gemm_body<false>(g_c_hi, g_c_lo, g_Wp_hi, g_Wp_lo, bias, out, CDIM);
}

// ---------------- HMMA flash attention: BQ=128, BK=64, d=64, 8 warps ----------------
// (unchanged from R9 — accumulator reuse gap already 8 MMAs)
constexpr int FA_RS    = 144;
constexpr int FA_ARR   = 64 * FA_RS;        // 9216
constexpr int FA_STAGE = 4 * FA_ARR;        // 36864 (Khi|Klo|Vhi|Vlo)
constexpr int FA_NST   = 4;
constexpr int FA_MASK  = FA_NST * FA_STAGE; // 147456
constexpr int FA_SMEM  = FA_MASK + FA_NST * 256; // 148480
constexpr int FA_NBLK  = NTOK / 64;         // 32
constexpr float FA_SCL = 0.18033688f;       // 0.125 * log2(e)

__device__ __forceinline__ void fa_load_stage(uint32_t su, int tid,
                                              const __nv_bfloat16* Khi,
                                              const __nv_bfloat16* Klo,
                                              const __nv_bfloat16* Vhi,
                                              const __nv_bfloat16* Vlo,
                                              const int* msrc, int blk)
{
    const uint32_t sb = su + (uint32_t)(blk & (FA_NST - 1)) * FA_STAGE;
    const size_t off = (size_t)blk * 64 * 64;
    const __nv_bfloat16* srcs[4] = { Khi + off, Klo + off, Vhi + off, Vlo + off };
#pragma unroll
    for (int i = 0; i < 8; i++) {
        int g = i * 256 + tid;
        int arr = g >> 9;
        int e = g & 511;
        int r = e >> 3;
        int ch = e & 7;
        cp_async16(sb + arr * FA_ARR + r * FA_RS + ch * 16,
                   srcs[arr] + (size_t)r * 64 + ch * 8);
    }
    if (tid < 16)
        cp_async16(su + FA_MASK + (uint32_t)(blk & (FA_NST - 1)) * 256 + tid * 16,
                   msrc + blk * 64 + tid * 4);
    asm volatile("cp.async.commit_group;");
}

__global__ void __launch_bounds__(256)
flash_mma_kernel(const int* __restrict__ mask)
{
    extern __shared__ char smem[];
    const uint32_t su = smem_u32(smem);
    const int tid = threadIdx.x;
    const int wid = tid >> 5, lane = tid & 31;
    const int b = blockIdx.z, h = blockIdx.y;
    const int q0 = blockIdx.x * 128;
    const size_t bh = (size_t)(b * HEADS + h);

    const __nv_bfloat16* Qhi = g_q_hi + (bh * NTOK + q0) * 64;
    const __nv_bfloat16* Qlo = g_q_lo + (bh * NTOK + q0) * 64;
    const __nv_bfloat16* Khi = g_k_hi + bh * NTOK * 64;
    const __nv_bfloat16* Klo = g_k_lo + bh * NTOK * 64;
    const __nv_bfloat16* Vhi = g_v_hi + bh * NTOK * 64;
    const __nv_bfloat16* Vlo = g_v_lo + bh * NTOK * 64;
    const int* msrc = mask + b * NTOK;

#pragma unroll
    for (int i = 0; i < 8; i++) {
        int g = i * 256 + tid;
        int arr = g >> 10;
        int e = g & 1023;
        int r = e >> 3;
        int ch = e & 7;
        cp_async16(su + arr * 18432 + r * FA_RS + ch * 16,
                   (arr ? Qlo : Qhi) + (size_t)r * 64 + ch * 8);
    }
    asm volatile("cp.async.commit_group;");
    asm volatile("cp.async.wait_group 0;" ::: "memory");
    __syncthreads();

    uint32_t qh[4][4], ql[4][4];
    {
        const int ar = wid * 16 + (lane & 15);
        const uint32_t ab = (uint32_t)((lane >> 4) << 4);
#pragma unroll
        for (int ks = 0; ks < 4; ks++) {
            uint32_t base = (uint32_t)(ar * FA_RS) + ab + ks * 32;
            ldsm_x4(qh[ks][0], qh[ks][1], qh[ks][2], qh[ks][3], su + base);
            ldsm_x4(ql[ks][0], ql[ks][1], ql[ks][2], ql[ks][3], su + 18432 + base);
        }
    }
    __syncthreads();

    float O[8][4];
#pragma unroll
    for (int t = 0; t < 8; t++)
#pragma unroll
        for (int f = 0; f < 4; f++) O[t][f] = 0.f;
    float m0 = -1e30f, m1 = -1e30f, l0 = 0.f, l1 = 0.f;

    fa_load_stage(su, tid, Khi, Klo, Vhi, Vlo, msrc, 0);
    fa_load_stage(su, tid, Khi, Klo, Vhi, Vlo, msrc, 1);
    fa_load_stage(su, tid, Khi, Klo, Vhi, Vlo, msrc, 2);

    const int kb_row = (lane & 7) | ((lane & 16) >> 1);
    const uint32_t kb_off = (uint32_t)((lane & 8) << 1);
    const int v_row = lane & 15;
    const uint32_t v_off = (uint32_t)(((lane & 16) >> 4) * 16);

    for (int blk = 0; blk < FA_NBLK; blk++) {
        if (blk < FA_NBLK - 2)       asm volatile("cp.async.wait_group 2;" ::: "memory");
        else if (blk == FA_NBLK - 2) asm volatile("cp.async.wait_group 1;" ::: "memory");
        else                         asm volatile("cp.async.wait_group 0;" ::: "memory");
        __syncthreads();
        if (blk + 3 < FA_NBLK) fa_load_stage(su, tid, Khi, Klo, Vhi, Vlo, msrc, blk + 3);

        const uint32_t sb = su + (uint32_t)(blk & (FA_NST - 1)) * FA_STAGE;

        float S[8][4];
#pragma unroll
        for (int t = 0; t < 8; t++)
#pragma unroll
            for (int f = 0; f < 4; f++) S[t][f] = 0.f;

#pragma unroll
        for (int ks = 0; ks < 4; ks++) {
            uint32_t kh[4][4], kl[4][4];
#pragma unroll
            for (int np = 0; np < 4; np++) {
                uint32_t base = (uint32_t)((np * 16 + kb_row) * FA_RS) + kb_off + ks * 32;
                ldsm_x4(kh[np][0], kh[np][1], kh[np][2], kh[np][3], sb + 0 * FA_ARR + base);
                ldsm_x4(kl[np][0], kl[np][1], kl[np][2], kl[np][3], sb + 1 * FA_ARR + base);
            }
#pragma unroll
            for (int np = 0; np < 4; np++) {
                mma_bf16(S[2 * np],     qh[ks], &kh[np][0]);
                mma_bf16(S[2 * np + 1], qh[ks], &kh[np][2]);
            }
#pragma unroll
            for (int np = 0; np < 4; np++) {
                mma_bf16(S[2 * np],     ql[ks], &kh[np][0]);
                mma_bf16(S[2 * np + 1], ql[ks], &kh[np][2]);
            }
#pragma unroll
            for (int np = 0; np < 4; np++) {
                mma_bf16(S[2 * np],     qh[ks], &kl[np][0]);
                mma_bf16(S[2 * np + 1], qh[ks], &kl[np][2]);
            }
        }

        const int* mrow = reinterpret_cast<const int*>(smem + FA_MASK + (blk & (FA_NST - 1)) * 256);
        float mx0 = -1e30f, mx1 = -1e30f;
#pragma unroll
        for (int t = 0; t < 8; t++) {
            int c0 = t * 8 + (lane & 3) * 2;
            float k0m = (mrow[c0] == 0) ? -1e30f : 0.f;
            float k1m = (mrow[c0 + 1] == 0) ? -1e30f : 0.f;
            S[t][0] = S[t][0] * FA_SCL + k0m;
            S[t][1] = S[t][1] * FA_SCL + k1m;
            S[t][2] = S[t][2] * FA_SCL + k0m;
            S[t][3] = S[t][3] * FA_SCL + k1m;
            mx0 = fmaxf(mx0, fmaxf(S[t][0], S[t][1]));
            mx1 = fmaxf(mx1, fmaxf(S[t][2], S[t][3]));
        }
#pragma unroll
        for (int off = 1; off <= 2; off <<= 1) {
            mx0 = fmaxf(mx0, __shfl_xor_sync(0xffffffffu, mx0, off));
            mx1 = fmaxf(mx1, __shfl_xor_sync(0xffffffffu, mx1, off));
        }
        float mn0 = fmaxf(m0, mx0), mn1 = fmaxf(m1, mx1);
        float al0 = ex2(m0 - mn0), al1 = ex2(m1 - mn1);
        m0 = mn0; m1 = mn1;
        float s0 = 0.f, s1 = 0.f;
#pragma unroll
        for (int t = 0; t < 8; t++) {
            S[t][0] = ex2(S[t][0] - mn0);
            S[t][1] = ex2(S[t][1] - mn0);
            S[t][2] = ex2(S[t][2] - mn1);
            S[t][3] = ex2(S[t][3] - mn1);
            s0 += S[t][0] + S[t][1];
            s1 += S[t][2] + S[t][3];
        }
#pragma unroll
        for (int off = 1; off <= 2; off <<= 1) {
            s0 += __shfl_xor_sync(0xffffffffu, s0, off);
            s1 += __shfl_xor_sync(0xffffffffu, s1, off);
        }
        l0 = l0 * al0 + s0;
        l1 = l1 * al1 + s1;
#pragma unroll
        for (int t = 0; t < 8; t++) {
            O[t][0] *= al0; O[t][1] *= al0;
            O[t][2] *= al1; O[t][3] *= al1;
        }

        uint32_t ph[4][4], pl[4][4];
#pragma unroll
        for (int s = 0; s < 4; s++) {
#pragma unroll
            for (int half = 0; half < 2; half++) {
#pragma unroll
                for (int rr = 0; rr < 2; rr++) {
                    float p0 = S[2 * s + half][rr * 2 + 0];
                    float p1 = S[2 * s + half][rr * 2 + 1];
                    __nv_bfloat16 h0, lo0, h1, lo1;
                    split2(p0, h0, lo0);
                    split2(p1, h1, lo1);
                    int ri = half * 2 + rr;
                    __nv_bfloat162 vh(h0, h1), vl(lo0, lo1);
                    ph[s][ri] = *reinterpret_cast<uint32_t*>(&vh);
                    pl[s][ri] = *reinterpret_cast<uint32_t*>(&vl);
                }
            }
        }

#pragma unroll
        for (int s = 0; s < 4; s++) {
            uint32_t vh[4][4], vl[4][4];
#pragma unroll
            for (int np = 0; np < 4; np++) {
                uint32_t base = (uint32_t)((16 * s + v_row) * FA_RS) + np * 32 + v_off;
                ldsm_x4_t(vh[np][0], vh[np][1], vh[np][2], vh[np][3], sb + 2 * FA_ARR + base);
                ldsm_x4_t(vl[np][0], vl[np][1], vl[np][2], vl[np][3], sb + 3 * FA_ARR + base);
            }
#pragma unroll
            for (int np = 0; np < 4; np++) {
                mma_bf16(O[2 * np],     ph[s], &vh[np][0]);
                mma_bf16(O[2 * np + 1], ph[s], &vh[np][2]);
            }
#pragma unroll
            for (int np = 0; np < 4; np++) {
                mma_bf16(O[2 * np],     pl[s], &vh[np][0]);
                mma_bf16(O[2 * np + 1], pl[s], &vh[np][2]);
            }
#pragma unroll
            for (int np = 0; np < 4; np++) {
                mma_bf16(O[2 * np],     ph[s], &vl[np][0]);
                mma_bf16(O[2 * np + 1], ph[s], &vl[np][2]);
            }
        }
    }

    const float inv0 = 1.0f / l0, inv1 = 1.0f / l1;
    const int r0 = q0 + wid * 16 + (lane >> 2);
    __nv_bfloat162* chi = reinterpret_cast<__nv_bfloat162*>(g_c_hi);
    __nv_bfloat162* clo = reinterpret_cast<__nv_bfloat162*>(g_c_lo);
#pragma unroll
    for (int t = 0; t < 8; t++) {
        int d = t * 8 + (lane & 3) * 2;
        size_t di0 = (((size_t)(b * NTOK + r0) * CDIM) + h * 64 + d) >> 1;
        size_t di1 = (((size_t)(b * NTOK + r0 + 8) * CDIM) + h * 64 + d) >> 1;
        float v0 = O[t][0] * inv0, v1 = O[t][1] * inv0;
        float v2 = O[t][2] * inv1, v3 = O[t][3] * inv1;
        __nv_bfloat16 h0, lo0, h1, lo1;
        split2(v0, h0, lo0); split2(v1, h1, lo1);
        chi[di0] = __nv_bfloat162(h0, h1);
        clo[di0] = __nv_bfloat162(lo0, lo1);
        split2(v2, h0, lo0); split2(v3, h1, lo1);
        chi[di1] = __nv_bfloat162(h0, h1);
        clo[di1] = __nv_bfloat162(lo0, lo1);
    }
}

// ---------------- launch ----------------
extern "C" void kernel_launch(void* const* d_in, const int* in_sizes, int n_in,
                              void* d_out, int out_size)
{
    (void)in_sizes; (void)n_in; (void)out_size;
    const float* x    = (const float*)d_in[0];
    const int*   mask = (const int*)d_in[1];
    const float* Wqkv = (const float*)d_in[2];
    const float* bqkv = (const float*)d_in[3];
    const float* Aqkv = (const float*)d_in[4];
    const float* Bqkv = (const float*)d_in[5];
    const float* Wp   = (const float*)d_in[6];
    const float* bp   = (const float*)d_in[7];
    const float* Ap   = (const float*)d_in[8];
    const float* Bp   = (const float*)d_in[9];
    float* out = (float*)d_out;

    fuse_qkv_kernel<<<(QKVC * CDIM + 255) / 256, 256>>>(Wqkv, Bqkv, Aqkv);
    fuse_p_kernel<<<(CDIM * CDIM + 255) / 256, 256>>>(Wp, Bp, Ap);
    cvt_x_kernel<<<(MROWS * CDIM + 255) / 256, 256>>>(x);

    cudaFuncSetAttribute(mma_gemm_qkv, cudaFuncAttributeMaxDynamicSharedMemorySize, GM_SMEM);
    mma_gemm_qkv<<<dim3(QKVC / 128, MROWS / 128), 256, GM_SMEM>>>(bqkv);

    cudaFuncSetAttribute(flash_mma_kernel, cudaFuncAttributeMaxDynamicSharedMemorySize, FA_SMEM);
    flash_mma_kernel<<<dim3(NTOK / 128, HEADS, BATCH), 256, FA_SMEM>>>(mask);

    cudaFuncSetAttribute(mma_gemm_proj, cudaFuncAttributeMaxDynamicSharedMemorySize, GM_SMEM);
    mma_gemm_proj<<<dim3(CDIM / 128, MROWS / 128), 256, GM_SMEM>>>(bp, out);
}

// round 11
// speedup vs baseline: 1.5829x; 1.5039x over previous
#include <cuda_runtime.h>
#include <cuda_fp16.h>
#include <cstdint>

// ---------------- problem constants ----------------
constexpr int BATCH = 2;
constexpr int NTOK  = 2048;
constexpr int CDIM  = 1024;
constexpr int HEADS = 16;
constexpr int MROWS = BATCH * NTOK;     // 4096
constexpr int QKVC  = 3 * CDIM;         // 3072

// ---------------- scratch (device globals, no allocation) ----------------
__device__ __half g_x_hi[MROWS * CDIM];
__device__ __half g_x_lo[MROWS * CDIM];
__device__ __half g_Wq_hi[QKVC * CDIM];
__device__ __half g_Wp_hi[CDIM * CDIM];
// q needs hi+lo (A-side of QK^T); k/v only hi (B-side / dropped-lo)
__device__ __half g_q_hi[MROWS * CDIM];
__device__ __half g_q_lo[MROWS * CDIM];
__device__ __half g_k_hi[MROWS * CDIM];
__device__ __half g_v_hi[MROWS * CDIM];
// ctx needs hi+lo (A-side of proj)
__device__ __half g_c_hi[MROWS * CDIM];
__device__ __half g_c_lo[MROWS * CDIM];

// ---------------- helpers ----------------
__device__ __forceinline__ void split2h(float v, __half& h, __half& l)
{
    h = __float2half_rn(v);
    l = __float2half_rn(v - __half2float(h));
}

__device__ __forceinline__ uint32_t smem_u32(const void* p)
{
    uint32_t a;
    asm("{ .reg .u64 t; cvta.to.shared.u64 t, %1; cvt.u32.u64 %0, t; }" : "=r"(a) : "l"(p));
    return a;
}

__device__ __forceinline__ void cp_async16(uint32_t dst, const void* src)
{
    asm volatile("cp.async.cg.shared.global [%0], [%1], 16;" :: "r"(dst), "l"(src));
}

__device__ __forceinline__ void ldsm_x4(uint32_t& r0, uint32_t& r1, uint32_t& r2, uint32_t& r3,
                                        uint32_t addr)
{
    asm volatile("ldmatrix.sync.aligned.m8n8.x4.shared.b16 {%0,%1,%2,%3}, [%4];"
                 : "=r"(r0), "=r"(r1), "=r"(r2), "=r"(r3) : "r"(addr));
}

__device__ __forceinline__ void ldsm_x4_t(uint32_t& r0, uint32_t& r1, uint32_t& r2, uint32_t& r3,
                                          uint32_t addr)
{
    asm volatile("ldmatrix.sync.aligned.m8n8.x4.trans.shared.b16 {%0,%1,%2,%3}, [%4];"
                 : "=r"(r0), "=r"(r1), "=r"(r2), "=r"(r3) : "r"(addr));
}

__device__ __forceinline__ void mma_f16(float* c, const uint32_t* a, const uint32_t* b)
{
    asm volatile("mma.sync.aligned.m16n8k16.row.col.f32.f16.f16.f32 "
                 "{%0,%1,%2,%3}, {%4,%5,%6,%7}, {%8,%9}, {%0,%1,%2,%3};"
                 : "+f"(c[0]), "+f"(c[1]), "+f"(c[2]), "+f"(c[3])
                 : "r"(a[0]), "r"(a[1]), "r"(a[2]), "r"(a[3]), "r"(b[0]), "r"(b[1]));
}

__device__ __forceinline__ float ex2(float x)
{
    float r;
    asm("ex2.approx.ftz.f32 %0, %1;" : "=f"(r) : "f"(x));
    return r;
}

// ---------------- conversion kernel ----------------
__global__ void cvt_x_kernel(const float* __restrict__ x)
{
    int i = blockIdx.x * blockDim.x + threadIdx.x;
    if (i < MROWS * CDIM) split2h(x[i], g_x_hi[i], g_x_lo[i]);
}

// ---------------- weight fusion: Weff = W + 2 * B @ A -> hi only ----------------
__device__ __forceinline__ void fuse_body(const float* __restrict__ W,
                                          const float* __restrict__ Bm,
                                          const float* __restrict__ A,
                                          __half* __restrict__ Whi, int total)
{
    int idx = blockIdx.x * blockDim.x + threadIdx.x;
    if (idx >= total) return;
    int i = idx >> 10;
    int j = idx & 1023;
    float s = 0.f;
#pragma unroll
    for (int r = 0; r < 16; r++) s += Bm[i * 16 + r] * A[r * CDIM + j];
    Whi[idx] = __float2half_rn(W[idx] + 2.0f * s);
}

__global__ void fuse_qkv_kernel(const float* __restrict__ W, const float* __restrict__ Bm,
                                const float* __restrict__ A)
{
    fuse_body(W, Bm, A, g_Wq_hi, QKVC * CDIM);
}

__global__ void fuse_p_kernel(const float* __restrict__ W, const float* __restrict__ Bm,
                              const float* __restrict__ A)
{
    fuse_body(W, Bm, A, g_Wp_hi, CDIM * CDIM);
}

// ---------------- HMMA GEMM (128x128 tile, 8 warps, 2-term fp16 split) --------------
// C = (Ahi + Alo) @ Bhi^T : residual A*B_lo ~ 2^-12. 2-stage pipeline, 2 CTAs/SM.
constexpr int GM_RS    = 80;
constexpr int GM_ARR   = 128 * GM_RS;        // 10240
constexpr int GM_STAGE = 3 * GM_ARR;         // 30720 (Ahi|Alo|Bhi)
constexpr int GM_SMEM  = 2 * GM_STAGE;       // 61440 (x2 CTAs fits easily)
constexpr int KCH      = 32;
constexpr int NCHUNK   = 1024 / KCH;         // 32

__device__ __forceinline__ void gm_load_chunk(uint32_t su, int tid,
                                              const __half* const* srcs, int c)
{
    uint32_t stage = su + (uint32_t)(c & 1) * GM_STAGE;
    int k0 = c * KCH;
#pragma unroll
    for (int i = 0; i < 6; i++) {
        int g = i * 256 + tid;     // 0..1535
        int t = g >> 9;            // array 0..2
        int e = g & 511;
        int r = e >> 2;
        int c16 = e & 3;
        cp_async16(stage + t * GM_ARR + r * GM_RS + c16 * 16,
                   srcs[t] + (size_t)r * 1024 + k0 + c16 * 8);
    }
    asm volatile("cp.async.commit_group;");
}

template <bool QKV_SPLIT_OUT>
__device__ __forceinline__ void mma_gemm_body(const __half* __restrict__ Ahi,
                                              const __half* __restrict__ Alo,
                                              const __half* __restrict__ Bhi,
                                              const float* __restrict__ bias,
                                              float* __restrict__ C, int Nc)
{
    extern __shared__ char smem[];
    const uint32_t su = smem_u32(smem);
    const int tid = threadIdx.x;
    const int wid = tid >> 5, lane = tid & 31;
    const int warp_m = wid >> 2, warp_n = wid & 3;
    const int row0 = blockIdx.y * 128;
    const int col0 = blockIdx.x * 128;

    const __half* srcs[3] = {
        Ahi + (size_t)row0 * 1024, Alo + (size_t)row0 * 1024,
        Bhi + (size_t)col0 * 1024 };

    float acc[4][4][4];
#pragma unroll
    for (int mt = 0; mt < 4; mt++)
#pragma unroll
        for (int nt = 0; nt < 4; nt++)
#pragma unroll
            for (int f = 0; f < 4; f++) acc[mt][nt][f] = 0.f;

    gm_load_chunk(su, tid, srcs, 0);

    const int a_row = warp_m * 64 + (lane & 15);
    const int a_kb  = (lane >> 4) << 4;
    const int b_row = warp_n * 32 + ((lane & 7) | ((lane & 16) >> 1));
    const int b_kb  = (lane & 8) << 1;

    for (int c = 0; c < NCHUNK; c++) {
        if (c + 1 < NCHUNK) {
            __syncthreads();
            gm_load_chunk(su, tid, srcs, c + 1);
            asm volatile("cp.async.wait_group 1;" ::: "memory");
        } else {
            asm volatile("cp.async.wait_group 0;" ::: "memory");
        }
        __syncthreads();

        const uint32_t stage = su + (uint32_t)(c & 1) * GM_STAGE;
#pragma unroll
        for (int ks = 0; ks < 2; ks++) {
            const uint32_t koff = ks * 32;

            uint32_t ah[4][4], al[4][4];
#pragma unroll
            for (int mt = 0; mt < 4; mt++) {
                uint32_t base = (uint32_t)((a_row + mt * 16) * GM_RS + a_kb + koff);
                ldsm_x4(ah[mt][0], ah[mt][1], ah[mt][2], ah[mt][3], stage + 0 * GM_ARR + base);
                ldsm_x4(al[mt][0], al[mt][1], al[mt][2], al[mt][3], stage + 1 * GM_ARR + base);
            }
            uint32_t bh[4][2];
#pragma unroll
            for (int np = 0; np < 2; np++) {
                uint32_t base = (uint32_t)((b_row + np * 16) * GM_RS + b_kb + koff);
                uint32_t r0, r1, r2, r3;
                ldsm_x4(r0, r1, r2, r3, stage + 2 * GM_ARR + base);
                bh[np * 2][0] = r0; bh[np * 2][1] = r1;
                bh[np * 2 + 1][0] = r2; bh[np * 2 + 1][1] = r3;
            }
#pragma unroll
            for (int term = 0; term < 2; term++)
#pragma unroll
                for (int mt = 0; mt < 4; mt++)
#pragma unroll
                    for (int nt = 0; nt < 4; nt++)
                        mma_f16(acc[mt][nt], term ? al[mt] : ah[mt], bh[nt]);
        }
    }

    if (!QKV_SPLIT_OUT) {
#pragma unroll
        for (int mt = 0; mt < 4; mt++) {
            int rg = row0 + warp_m * 64 + mt * 16 + (lane >> 2);
#pragma unroll
            for (int nt = 0; nt < 4; nt++) {
                int cg = col0 + warp_n * 32 + nt * 8 + (lane & 3) * 2;
                float b0 = bias[cg], b1 = bias[cg + 1];
                float2 v0 = make_float2(acc[mt][nt][0] + b0, acc[mt][nt][1] + b1);
                float2 v1 = make_float2(acc[mt][nt][2] + b0, acc[mt][nt][3] + b1);
                *reinterpret_cast<float2*>(&C[(size_t)rg * Nc + cg]) = v0;
                *reinterpret_cast<float2*>(&C[(size_t)(rg + 8) * Nc + cg]) = v1;
            }
        }
    } else {
        __half2* qhi2 = reinterpret_cast<__half2*>(g_q_hi);
        __half2* qlo2 = reinterpret_cast<__half2*>(g_q_lo);
        __half2* khi2 = reinterpret_cast<__half2*>(g_k_hi);
        __half2* vhi2 = reinterpret_cast<__half2*>(g_v_hi);
#pragma unroll
        for (int nt = 0; nt < 4; nt++) {
            int cg = col0 + warp_n * 32 + nt * 8 + (lane & 3) * 2;
            int which = cg >> 10;      // 0=q 1=k 2=v
            int rem = cg & 1023;
            int h = rem >> 6;
            int d = rem & 63;
            float b0 = bias[cg], b1 = bias[cg + 1];
#pragma unroll
            for (int mt = 0; mt < 4; mt++) {
                int rbase = row0 + warp_m * 64 + mt * 16 + (lane >> 2);
#pragma unroll
                for (int half_i = 0; half_i < 2; half_i++) {
                    int r = rbase + half_i * 8;
                    int bb = r >> 11, n = r & 2047;
                    size_t di = (((size_t)((bb << 4) + h) * 2048 + n) * 64 + d) >> 1;
                    float v0 = acc[mt][nt][half_i * 2 + 0] + b0;
                    float v1 = acc[mt][nt][half_i * 2 + 1] + b1;
                    if (which == 0) {
                        __half h0, l0, h1, l1;
                        split2h(v0, h0, l0);
                        split2h(v1, h1, l1);
                        qhi2[di] = __halves2half2(h0, h1);
                        qlo2[di] = __halves2half2(l0, l1);
                    } else if (which == 1) {
                        khi2[di] = __floats2half2_rn(v0, v1);
                    } else {
                        vhi2[di] = __floats2half2_rn(v0, v1);
                    }
                }
            }
        }
    }
}

__global__ void __launch_bounds__(256, 2)
mma_gemm_qkv(const float* __restrict__ bias)
{
    mma_gemm_body<true>(g_x_hi, g_x_lo, g_Wq_hi, bias, nullptr, QKVC);
}

__global__ void __launch_bounds__(256, 2)
mma_gemm_proj(const float* __restrict__ bias, float* __restrict__ out)
{
    mma_gemm_body<false>(g_c_hi, g_c_lo, g_Wp_hi, bias, out, CDIM);
}

// ---------------- HMMA flash attention: BQ=128, BK=64, d=64, 8 warps ----------------
// fp16 2-term: S = (q_hi+q_lo) k_hi ; O = (p_hi+p_lo) v_hi. 4-stage, base-2 softmax.
constexpr int FA_RS    = 144;
constexpr int FA_ARR   = 64 * FA_RS;        // 9216
constexpr int FA_STAGE = 2 * FA_ARR;        // 18432 (Khi|Vhi)
constexpr int FA_NST   = 4;
constexpr int FA_MASK  = FA_NST * FA_STAGE; // 73728
constexpr int FA_SMEM  = FA_MASK + FA_NST * 256; // 74752
constexpr int FA_NBLK  = NTOK / 64;         // 32
constexpr float FA_SCL = 0.18033688f;       // 0.125 * log2(e)

__device__ __forceinline__ void fa_load_stage(uint32_t su, int tid,
                                              const __half* Khi, const __half* Vhi,
                                              const int* msrc, int blk)
{
    const uint32_t sb = su + (uint32_t)(blk & (FA_NST - 1)) * FA_STAGE;
    const size_t off = (size_t)blk * 64 * 64;
    const __half* srcs[2] = { Khi + off, Vhi + off };
#pragma unroll
    for (int i = 0; i < 4; i++) {
        int g = i * 256 + tid;     // 0..1023
        int arr = g >> 9;          // 0..1
        int e = g & 511;
        int r = e >> 3;
        int ch = e & 7;
        cp_async16(sb + arr * FA_ARR + r * FA_RS + ch * 16,
                   srcs[arr] + (size_t)r * 64 + ch * 8);
    }
    if (tid < 16)
        cp_async16(su + FA_MASK + (uint32_t)(blk & (FA_NST - 1)) * 256 + tid * 16,
                   msrc + blk * 64 + tid * 4);
    asm volatile("cp.async.commit_group;");
}

__global__ void __launch_bounds__(256)
flash_mma_kernel(const int* __restrict__ mask)
{
    extern __shared__ char smem[];
    const uint32_t su = smem_u32(smem);
    const int tid = threadIdx.x;
    const int wid = tid >> 5, lane = tid & 31;
    const int b = blockIdx.z, h = blockIdx.y;
    const int q0 = blockIdx.x * 128;
    const size_t bh = (size_t)(b * HEADS + h);

    const __half* Qhi = g_q_hi + (bh * NTOK + q0) * 64;
    const __half* Qlo = g_q_lo + (bh * NTOK + q0) * 64;
    const __half* Khi = g_k_hi + bh * NTOK * 64;
    const __half* Vhi = g_v_hi + bh * NTOK * 64;
    const int* msrc = mask + b * NTOK;

    // stage Q (hi at su, lo at su+18432), pull to regs, then region is reused by K/V stages
#pragma unroll
    for (int i = 0; i < 8; i++) {
        int g = i * 256 + tid;
        int arr = g >> 10;
        int e = g & 1023;
        int r = e >> 3;
        int ch = e & 7;
        cp_async16(su + arr * 18432 + r * FA_RS + ch * 16,
                   (arr ? Qlo : Qhi) + (size_t)r * 64 + ch * 8);
    }
    asm volatile("cp.async.commit_group;");
    asm volatile("cp.async.wait_group 0;" ::: "memory");
    __syncthreads();

    uint32_t qh[4][4], ql[4][4];
    {
        const int ar = wid * 16 + (lane & 15);
        const uint32_t ab = (uint32_t)((lane >> 4) << 4);
#pragma unroll
        for (int ks = 0; ks < 4; ks++) {
            uint32_t base = (uint32_t)(ar * FA_RS) + ab + ks * 32;
            ldsm_x4(qh[ks][0], qh[ks][1], qh[ks][2], qh[ks][3], su + base);
            ldsm_x4(ql[ks][0], ql[ks][1], ql[ks][2], ql[ks][3], su + 18432 + base);
        }
    }
    __syncthreads();

    float O[8][4];
#pragma unroll
    for (int t = 0; t < 8; t++)
#pragma unroll
        for (int f = 0; f < 4; f++) O[t][f] = 0.f;
    float m0 = -1e30f, m1 = -1e30f, l0 = 0.f, l1 = 0.f;

    fa_load_stage(su, tid, Khi, Vhi, msrc, 0);
    fa_load_stage(su, tid, Khi, Vhi, msrc, 1);
    fa_load_stage(su, tid, Khi, Vhi, msrc, 2);

    const int kb_row = (lane & 7) | ((lane & 16) >> 1);
    const uint32_t kb_off = (uint32_t)((lane & 8) << 1);
    const int v_row = lane & 15;
    const uint32_t v_off = (uint32_t)(((lane & 16) >> 4) * 16);

    for (int blk = 0; blk < FA_NBLK; blk++) {
        if (blk < FA_NBLK - 2)       asm volatile("cp.async.wait_group 2;" ::: "memory");
        else if (blk == FA_NBLK - 2) asm volatile("cp.async.wait_group 1;" ::: "memory");
        else                         asm volatile("cp.async.wait_group 0;" ::: "memory");
        __syncthreads();
        if (blk + 3 < FA_NBLK) fa_load_stage(su, tid, Khi, Vhi, msrc, blk + 3);

        const uint32_t sb = su + (uint32_t)(blk & (FA_NST - 1)) * FA_STAGE;

        // ---- S = Q K^T (2-term) ----
        float S[8][4];
#pragma unroll
        for (int t = 0; t < 8; t++)
#pragma unroll
            for (int f = 0; f < 4; f++) S[t][f] = 0.f;

#pragma unroll
        for (int ks = 0; ks < 4; ks++) {
            uint32_t kh[4][4];
#pragma unroll
            for (int np = 0; np < 4; np++) {
                uint32_t base = (uint32_t)((np * 16 + kb_row) * FA_RS) + kb_off + ks * 32;
                ldsm_x4(kh[np][0], kh[np][1], kh[np][2], kh[np][3], sb + base);
            }
#pragma unroll
            for (int np = 0; np < 4; np++) {
                mma_f16(S[2 * np],     qh[ks], &kh[np][0]);
                mma_f16(S[2 * np + 1], qh[ks], &kh[np][2]);
            }
#pragma unroll
            for (int np = 0; np < 4; np++) {
                mma_f16(S[2 * np],     ql[ks], &kh[np][0]);
                mma_f16(S[2 * np + 1], ql[ks], &kh[np][2]);
            }
        }

        // ---- mask + online softmax (base-2) ----
        const int* mrow = reinterpret_cast<const int*>(smem + FA_MASK + (blk & (FA_NST - 1)) * 256);
        float mx0 = -1e30f, mx1 = -1e30f;
#pragma unroll
        for (int t = 0; t < 8; t++) {
            int c0 = t * 8 + (lane & 3) * 2;
            float k0m = (mrow[c0] == 0) ? -1e30f : 0.f;
            float k1m = (mrow[c0 + 1] == 0) ? -1e30f : 0.f;
            S[t][0] = S[t][0] * FA_SCL + k0m;
            S[t][1] = S[t][1] * FA_SCL + k1m;
            S[t][2] = S[t][2] * FA_SCL + k0m;
            S[t][3] = S[t][3] * FA_SCL + k1m;
            mx0 = fmaxf(mx0, fmaxf(S[t][0], S[t][1]));
            mx1 = fmaxf(mx1, fmaxf(S[t][2], S[t][3]));
        }
#pragma unroll
        for (int off = 1; off <= 2; off <<= 1) {
            mx0 = fmaxf(mx0, __shfl_xor_sync(0xffffffffu, mx0, off));
            mx1 = fmaxf(mx1, __shfl_xor_sync(0xffffffffu, mx1, off));
        }
        float mn0 = fmaxf(m0, mx0), mn1 = fmaxf(m1, mx1);
        float al0 = ex2(m0 - mn0), al1 = ex2(m1 - mn1);
        m0 = mn0; m1 = mn1;
        float s0 = 0.f, s1 = 0.f;
#pragma unroll
        for (int t = 0; t < 8; t++) {
            S[t][0] = ex2(S[t][0] - mn0);
            S[t][1] = ex2(S[t][1] - mn0);
            S[t][2] = ex2(S[t][2] - mn1);
            S[t][3] = ex2(S[t][3] - mn1);
            s0 += S[t][0] + S[t][1];
            s1 += S[t][2] + S[t][3];
        }
#pragma unroll
        for (int off = 1; off <= 2; off <<= 1) {
            s0 += __shfl_xor_sync(0xffffffffu, s0, off);
            s1 += __shfl_xor_sync(0xffffffffu, s1, off);
        }
        l0 = l0 * al0 + s0;
        l1 = l1 * al1 + s1;
#pragma unroll
        for (int t = 0; t < 8; t++) {
            O[t][0] *= al0; O[t][1] *= al0;
            O[t][2] *= al1; O[t][3] *= al1;
        }

        // ---- pack P into hi/lo A-fragments ----
        uint32_t ph[4][4], pl[4][4];
#pragma unroll
        for (int s = 0; s < 4; s++) {
#pragma unroll
            for (int half_i = 0; half_i < 2; half_i++) {
#pragma unroll
                for (int rr = 0; rr < 2; rr++) {
                    float p0 = S[2 * s + half_i][rr * 2 + 0];
                    float p1 = S[2 * s + half_i][rr * 2 + 1];
                    __half h0, lo0, h1, lo1;
                    split2h(p0, h0, lo0);
                    split2h(p1, h1, lo1);
                    int ri = half_i * 2 + rr;
                    __half2 vh = __halves2half2(h0, h1), vl = __halves2half2(lo0, lo1);
                    ph[s][ri] = *reinterpret_cast<uint32_t*>(&vh);
                    pl[s][ri] = *reinterpret_cast<uint32_t*>(&vl);
                }
            }
        }

        // ---- O += P V (2-term) ----
#pragma unroll
        for (int s = 0; s < 4; s++) {
            uint32_t vh[4][4];
#pragma unroll
            for (int np = 0; np < 4; np++) {
                uint32_t base = (uint32_t)((16 * s + v_row) * FA_RS) + np * 32 + v_off;
                ldsm_x4_t(vh[np][0], vh[np][1], vh[np][2], vh[np][3], sb + FA_ARR + base);
            }
#pragma unroll
            for (int np = 0; np < 4; np++) {
                mma_f16(O[2 * np],     ph[s], &vh[np][0]);
                mma_f16(O[2 * np + 1], ph[s], &vh[np][2]);
            }
#pragma unroll
            for (int np = 0; np < 4; np++) {
                mma_f16(O[2 * np],     pl[s], &vh[np][0]);
                mma_f16(O[2 * np + 1], pl[s], &vh[np][2]);
            }
        }
    }

    // ---- normalize, split, write ctx [B][N][C] hi/lo ----
    const float inv0 = 1.0f / l0, inv1 = 1.0f / l1;
    const int r0 = q0 + wid * 16 + (lane >> 2);
    __half2* chi = reinterpret_cast<__half2*>(g_c_hi);
    __half2* clo = reinterpret_cast<__half2*>(g_c_lo);
#pragma unroll
    for (int t = 0; t < 8; t++) {
        int d = t * 8 + (lane & 3) * 2;
        size_t di0 = (((size_t)(b * NTOK + r0) * CDIM) + h * 64 + d) >> 1;
        size_t di1 = (((size_t)(b * NTOK + r0 + 8) * CDIM) + h * 64 + d) >> 1;
        float v0 = O[t][0] * inv0, v1 = O[t][1] * inv0;
        float v2 = O[t][2] * inv1, v3 = O[t][3] * inv1;
        __half h0, lo0, h1, lo1;
        split2h(v0, h0, lo0); split2h(v1, h1, lo1);
        chi[di0] = __halves2half2(h0, h1);
        clo[di0] = __halves2half2(lo0, lo1);
        split2h(v2, h0, lo0); split2h(v3, h1, lo1);
        chi[di1] = __halves2half2(h0, h1);
        clo[di1] = __halves2half2(lo0, lo1);
    }
}

// ---------------- launch ----------------
extern "C" void kernel_launch(void* const* d_in, const int* in_sizes, int n_in,
                              void* d_out, int out_size)
{
    (void)in_sizes; (void)n_in; (void)out_size;
    const float* x    = (const float*)d_in[0];
    const int*   mask = (const int*)d_in[1];
    const float* Wqkv = (const float*)d_in[2];
    const float* bqkv = (const float*)d_in[3];
    const float* Aqkv = (const float*)d_in[4];
    const float* Bqkv = (const float*)d_in[5];
    const float* Wp   = (const float*)d_in[6];
    const float* bp   = (const float*)d_in[7];
    const float* Ap   = (const float*)d_in[8];
    const float* Bp   = (const float*)d_in[9];
    float* out = (float*)d_out;

    fuse_qkv_kernel<<<(QKVC * CDIM + 255) / 256, 256>>>(Wqkv, Bqkv, Aqkv);
    fuse_p_kernel<<<(CDIM * CDIM + 255) / 256, 256>>>(Wp, Bp, Ap);
    cvt_x_kernel<<<(MROWS * CDIM + 255) / 256, 256>>>(x);

    cudaFuncSetAttribute(mma_gemm_qkv, cudaFuncAttributeMaxDynamicSharedMemorySize, GM_SMEM);
    mma_gemm_qkv<<<dim3(QKVC / 128, MROWS / 128), 256, GM_SMEM>>>(bqkv);

    cudaFuncSetAttribute(flash_mma_kernel, cudaFuncAttributeMaxDynamicSharedMemorySize, FA_SMEM);
    flash_mma_kernel<<<dim3(NTOK / 128, HEADS, BATCH), 256, FA_SMEM>>>(mask);

    cudaFuncSetAttribute(mma_gemm_proj, cudaFuncAttributeMaxDynamicSharedMemorySize, GM_SMEM);
    mma_gemm_proj<<<dim3(CDIM / 128, MROWS / 128), 256, GM_SMEM>>>(bp, out);
}

// round 12
// speedup vs baseline: 2.5950x; 1.6394x over previous
#include <cuda_runtime.h>
#include <cuda_fp16.h>
#include <cstdint>

// ---------------- problem constants ----------------
constexpr int BATCH = 2;
constexpr int NTOK  = 2048;
constexpr int CDIM  = 1024;
constexpr int HEADS = 16;
constexpr int MROWS = BATCH * NTOK;     // 4096
constexpr int QKVC  = 3 * CDIM;         // 3072

// ---------------- scratch (device globals, no allocation) ----------------
__device__ __half g_x[MROWS * CDIM];
__device__ __half g_Wq[QKVC * CDIM];
__device__ __half g_Wp[CDIM * CDIM];
__device__ __half g_q[MROWS * CDIM];
__device__ __half g_k[MROWS * CDIM];
__device__ __half g_v[MROWS * CDIM];
__device__ __half g_c[MROWS * CDIM];

// ---------------- helpers ----------------
__device__ __forceinline__ uint32_t smem_u32(const void* p)
{
    uint32_t a;
    asm("{ .reg .u64 t; cvta.to.shared.u64 t, %1; cvt.u32.u64 %0, t; }" : "=r"(a) : "l"(p));
    return a;
}

__device__ __forceinline__ void cp_async16(uint32_t dst, const void* src)
{
    asm volatile("cp.async.cg.shared.global [%0], [%1], 16;" :: "r"(dst), "l"(src));
}

__device__ __forceinline__ void ldsm_x4(uint32_t& r0, uint32_t& r1, uint32_t& r2, uint32_t& r3,
                                        uint32_t addr)
{
    asm volatile("ldmatrix.sync.aligned.m8n8.x4.shared.b16 {%0,%1,%2,%3}, [%4];"
                 : "=r"(r0), "=r"(r1), "=r"(r2), "=r"(r3) : "r"(addr));
}

__device__ __forceinline__ void ldsm_x4_t(uint32_t& r0, uint32_t& r1, uint32_t& r2, uint32_t& r3,
                                          uint32_t addr)
{
    asm volatile("ldmatrix.sync.aligned.m8n8.x4.trans.shared.b16 {%0,%1,%2,%3}, [%4];"
                 : "=r"(r0), "=r"(r1), "=r"(r2), "=r"(r3) : "r"(addr));
}

__device__ __forceinline__ void mma_f16(float* c, const uint32_t* a, const uint32_t* b)
{
    asm volatile("mma.sync.aligned.m16n8k16.row.col.f32.f16.f16.f32 "
                 "{%0,%1,%2,%3}, {%4,%5,%6,%7}, {%8,%9}, {%0,%1,%2,%3};"
                 : "+f"(c[0]), "+f"(c[1]), "+f"(c[2]), "+f"(c[3])
                 : "r"(a[0]), "r"(a[1]), "r"(a[2]), "r"(a[3]), "r"(b[0]), "r"(b[1]));
}

__device__ __forceinline__ float ex2(float x)
{
    float r;
    asm("ex2.approx.ftz.f32 %0, %1;" : "=f"(r) : "f"(x));
    return r;
}

// ---------------- conversion kernel ----------------
__global__ void cvt_x_kernel(const float* __restrict__ x)
{
    int i = blockIdx.x * blockDim.x + threadIdx.x;
    if (i < MROWS * CDIM) g_x[i] = __float2half_rn(x[i]);
}

// ---------------- weight fusion: Weff = W + 2 * B @ A ----------------
__device__ __forceinline__ void fuse_body(const float* __restrict__ W,
                                          const float* __restrict__ Bm,
                                          const float* __restrict__ A,
                                          __half* __restrict__ Wh, int total)
{
    int idx = blockIdx.x * blockDim.x + threadIdx.x;
    if (idx >= total) return;
    int i = idx >> 10;
    int j = idx & 1023;
    float s = 0.f;
#pragma unroll
    for (int r = 0; r < 16; r++) s += Bm[i * 16 + r] * A[r * CDIM + j];
    Wh[idx] = __float2half_rn(W[idx] + 2.0f * s);
}

__global__ void fuse_qkv_kernel(const float* __restrict__ W, const float* __restrict__ Bm,
                                const float* __restrict__ A)
{
    fuse_body(W, Bm, A, g_Wq, QKVC * CDIM);
}

__global__ void fuse_p_kernel(const float* __restrict__ W, const float* __restrict__ Bm,
                              const float* __restrict__ A)
{
    fuse_body(W, Bm, A, g_Wp, CDIM * CDIM);
}

// ---------------- HMMA GEMM (128x128 tile, 8 warps, pure fp16) ----------------------
constexpr int GM_RS    = 80;
constexpr int GM_ARR   = 128 * GM_RS;        // 10240
constexpr int GM_STAGE = 2 * GM_ARR;         // 20480 (A|B)
constexpr int GM_SMEM  = 2 * GM_STAGE;       // 40960
constexpr int KCH      = 32;
constexpr int NCHUNK   = 1024 / KCH;         // 32

__device__ __forceinline__ void gm_load_chunk(uint32_t su, int tid,
                                              const __half* const* srcs, int c)
{
    uint32_t stage = su + (uint32_t)(c & 1) * GM_STAGE;
    int k0 = c * KCH;
#pragma unroll
    for (int i = 0; i < 4; i++) {
        int g = i * 256 + tid;     // 0..1023
        int t = g >> 9;            // array 0..1
        int e = g & 511;
        int r = e >> 2;
        int c16 = e & 3;
        cp_async16(stage + t * GM_ARR + r * GM_RS + c16 * 16,
                   srcs[t] + (size_t)r * 1024 + k0 + c16 * 8);
    }
    asm volatile("cp.async.commit_group;");
}

template <bool QKV_SPLIT_OUT>
__device__ __forceinline__ void mma_gemm_body(const __half* __restrict__ Af,
                                              const __half* __restrict__ Bf,
                                              const float* __restrict__ bias,
                                              float* __restrict__ C, int Nc)
{
    extern __shared__ char smem[];
    const uint32_t su = smem_u32(smem);
    const int tid = threadIdx.x;
    const int wid = tid >> 5, lane = tid & 31;
    const int warp_m = wid >> 2, warp_n = wid & 3;
    const int row0 = blockIdx.y * 128;
    const int col0 = blockIdx.x * 128;

    const __half* srcs[2] = { Af + (size_t)row0 * 1024, Bf + (size_t)col0 * 1024 };

    float acc[4][4][4];
#pragma unroll
    for (int mt = 0; mt < 4; mt++)
#pragma unroll
        for (int nt = 0; nt < 4; nt++)
#pragma unroll
            for (int f = 0; f < 4; f++) acc[mt][nt][f] = 0.f;

    gm_load_chunk(su, tid, srcs, 0);

    const int a_row = warp_m * 64 + (lane & 15);
    const int a_kb  = (lane >> 4) << 4;
    const int b_row = warp_n * 32 + ((lane & 7) | ((lane & 16) >> 1));
    const int b_kb  = (lane & 8) << 1;

    for (int c = 0; c < NCHUNK; c++) {
        if (c + 1 < NCHUNK) {
            __syncthreads();
            gm_load_chunk(su, tid, srcs, c + 1);
            asm volatile("cp.async.wait_group 1;" ::: "memory");
        } else {
            asm volatile("cp.async.wait_group 0;" ::: "memory");
        }
        __syncthreads();

        const uint32_t stage = su + (uint32_t)(c & 1) * GM_STAGE;
#pragma unroll
        for (int ks = 0; ks < 2; ks++) {
            const uint32_t koff = ks * 32;

            uint32_t ah[4][4];
#pragma unroll
            for (int mt = 0; mt < 4; mt++) {
                uint32_t base = (uint32_t)((a_row + mt * 16) * GM_RS + a_kb + koff);
                ldsm_x4(ah[mt][0], ah[mt][1], ah[mt][2], ah[mt][3], stage + base);
            }
            uint32_t bh[4][2];
#pragma unroll
            for (int np = 0; np < 2; np++) {
                uint32_t base = (uint32_t)((b_row + np * 16) * GM_RS + b_kb + koff);
                uint32_t r0, r1, r2, r3;
                ldsm_x4(r0, r1, r2, r3, stage + GM_ARR + base);
                bh[np * 2][0] = r0; bh[np * 2][1] = r1;
                bh[np * 2 + 1][0] = r2; bh[np * 2 + 1][1] = r3;
            }
#pragma unroll
            for (int mt = 0; mt < 4; mt++)
#pragma unroll
                for (int nt = 0; nt < 4; nt++)
                    mma_f16(acc[mt][nt], ah[mt], bh[nt]);
        }
    }

    if (!QKV_SPLIT_OUT) {
#pragma unroll
        for (int mt = 0; mt < 4; mt++) {
            int rg = row0 + warp_m * 64 + mt * 16 + (lane >> 2);
#pragma unroll
            for (int nt = 0; nt < 4; nt++) {
                int cg = col0 + warp_n * 32 + nt * 8 + (lane & 3) * 2;
                float b0 = bias[cg], b1 = bias[cg + 1];
                float2 v0 = make_float2(acc[mt][nt][0] + b0, acc[mt][nt][1] + b1);
                float2 v1 = make_float2(acc[mt][nt][2] + b0, acc[mt][nt][3] + b1);
                *reinterpret_cast<float2*>(&C[(size_t)rg * Nc + cg]) = v0;
                *reinterpret_cast<float2*>(&C[(size_t)(rg + 8) * Nc + cg]) = v1;
            }
        }
    } else {
        __half2* q2 = reinterpret_cast<__half2*>(g_q);
        __half2* k2 = reinterpret_cast<__half2*>(g_k);
        __half2* v2 = reinterpret_cast<__half2*>(g_v);
#pragma unroll
        for (int nt = 0; nt < 4; nt++) {
            int cg = col0 + warp_n * 32 + nt * 8 + (lane & 3) * 2;
            int which = cg >> 10;      // 0=q 1=k 2=v
            int rem = cg & 1023;
            int h = rem >> 6;
            int d = rem & 63;
            float b0 = bias[cg], b1 = bias[cg + 1];
            __half2* dst = (which == 0) ? q2 : (which == 1) ? k2 : v2;
#pragma unroll
            for (int mt = 0; mt < 4; mt++) {
                int rbase = row0 + warp_m * 64 + mt * 16 + (lane >> 2);
#pragma unroll
                for (int half_i = 0; half_i < 2; half_i++) {
                    int r = rbase + half_i * 8;
                    int bb = r >> 11, n = r & 2047;
                    size_t di = (((size_t)((bb << 4) + h) * 2048 + n) * 64 + d) >> 1;
                    float v0 = acc[mt][nt][half_i * 2 + 0] + b0;
                    float v1 = acc[mt][nt][half_i * 2 + 1] + b1;
                    dst[di] = __floats2half2_rn(v0, v1);
                }
            }
        }
    }
}

__global__ void __launch_bounds__(256, 2)
mma_gemm_qkv(const float* __restrict__ bias)
{
    mma_gemm_body<true>(g_x, g_Wq, bias, nullptr, QKVC);
}

__global__ void __launch_bounds__(256, 2)
mma_gemm_proj(const float* __restrict__ bias, float* __restrict__ out)
{
    mma_gemm_body<false>(g_c, g_Wp, bias, out, CDIM);
}

// ---------------- HMMA flash attention: BQ=128, BK=64, d=64, 8 warps, pure fp16 -----
constexpr int FA_RS    = 144;
constexpr int FA_ARR   = 64 * FA_RS;        // 9216
constexpr int FA_STAGE = 2 * FA_ARR;        // 18432 (K|V)
constexpr int FA_NST   = 4;
constexpr int FA_MASK  = FA_NST * FA_STAGE; // 73728
constexpr int FA_SMEM  = FA_MASK + FA_NST * 256; // 74752
constexpr int FA_NBLK  = NTOK / 64;         // 32
constexpr float FA_SCL = 0.18033688f;       // 0.125 * log2(e)

__device__ __forceinline__ void fa_load_stage(uint32_t su, int tid,
                                              const __half* K, const __half* V,
                                              const int* msrc, int blk)
{
    const uint32_t sb = su + (uint32_t)(blk & (FA_NST - 1)) * FA_STAGE;
    const size_t off = (size_t)blk * 64 * 64;
    const __half* srcs[2] = { K + off, V + off };
#pragma unroll
    for (int i = 0; i < 4; i++) {
        int g = i * 256 + tid;     // 0..1023
        int arr = g >> 9;
        int e = g & 511;
        int r = e >> 3;
        int ch = e & 7;
        cp_async16(sb + arr * FA_ARR + r * FA_RS + ch * 16,
                   srcs[arr] + (size_t)r * 64 + ch * 8);
    }
    if (tid < 16)
        cp_async16(su + FA_MASK + (uint32_t)(blk & (FA_NST - 1)) * 256 + tid * 16,
                   msrc + blk * 64 + tid * 4);
    asm volatile("cp.async.commit_group;");
}

__global__ void __launch_bounds__(256)
flash_mma_kernel(const int* __restrict__ mask)
{
    extern __shared__ char smem[];
    const uint32_t su = smem_u32(smem);
    const int tid = threadIdx.x;
    const int wid = tid >> 5, lane = tid & 31;
    const int b = blockIdx.z, h = blockIdx.y;
    const int q0 = blockIdx.x * 128;
    const size_t bh = (size_t)(b * HEADS + h);

    const __half* Q = g_q + (bh * NTOK + q0) * 64;
    const __half* K = g_k + bh * NTOK * 64;
    const __half* V = g_v + bh * NTOK * 64;
    const int* msrc = mask + b * NTOK;

    // stage Q (128 x 64 fp16) at su, pull to regs, then region reused by K/V stages
#pragma unroll
    for (int i = 0; i < 4; i++) {
        int g = i * 256 + tid;     // 0..1023
        int r = g >> 3;            // row 0..127
        int ch = g & 7;
        cp_async16(su + r * FA_RS + ch * 16, Q + (size_t)r * 64 + ch * 8);
    }
    asm volatile("cp.async.commit_group;");
    asm volatile("cp.async.wait_group 0;" ::: "memory");
    __syncthreads();

    uint32_t qh[4][4];
    {
        const int ar = wid * 16 + (lane & 15);
        const uint32_t ab = (uint32_t)((lane >> 4) << 4);
#pragma unroll
        for (int ks = 0; ks < 4; ks++) {
            uint32_t base = (uint32_t)(ar * FA_RS) + ab + ks * 32;
            ldsm_x4(qh[ks][0], qh[ks][1], qh[ks][2], qh[ks][3], su + base);
        }
    }
    __syncthreads();

    float O[8][4];
#pragma unroll
    for (int t = 0; t < 8; t++)
#pragma unroll
        for (int f = 0; f < 4; f++) O[t][f] = 0.f;
    float m0 = -1e30f, m1 = -1e30f, l0 = 0.f, l1 = 0.f;

    fa_load_stage(su, tid, K, V, msrc, 0);
    fa_load_stage(su, tid, K, V, msrc, 1);
    fa_load_stage(su, tid, K, V, msrc, 2);

    const int kb_row = (lane & 7) | ((lane & 16) >> 1);
    const uint32_t kb_off = (uint32_t)((lane & 8) << 1);
    const int v_row = lane & 15;
    const uint32_t v_off = (uint32_t)(((lane & 16) >> 4) * 16);

    for (int blk = 0; blk < FA_NBLK; blk++) {
        if (blk < FA_NBLK - 2)       asm volatile("cp.async.wait_group 2;" ::: "memory");
        else if (blk == FA_NBLK - 2) asm volatile("cp.async.wait_group 1;" ::: "memory");
        else                         asm volatile("cp.async.wait_group 0;" ::: "memory");
        __syncthreads();
        if (blk + 3 < FA_NBLK) fa_load_stage(su, tid, K, V, msrc, blk + 3);

        const uint32_t sb = su + (uint32_t)(blk & (FA_NST - 1)) * FA_STAGE;

        // ---- S = Q K^T ----
        float S[8][4];
#pragma unroll
        for (int t = 0; t < 8; t++)
#pragma unroll
            for (int f = 0; f < 4; f++) S[t][f] = 0.f;

#pragma unroll
        for (int ks = 0; ks < 4; ks++) {
            uint32_t kh[4][4];
#pragma unroll
            for (int np = 0; np < 4; np++) {
                uint32_t base = (uint32_t)((np * 16 + kb_row) * FA_RS) + kb_off + ks * 32;
                ldsm_x4(kh[np][0], kh[np][1], kh[np][2], kh[np][3], sb + base);
            }
#pragma unroll
            for (int np = 0; np < 4; np++) {
                mma_f16(S[2 * np],     qh[ks], &kh[np][0]);
                mma_f16(S[2 * np + 1], qh[ks], &kh[np][2]);
            }
        }

        // ---- mask + online softmax (base-2) ----
        const int* mrow = reinterpret_cast<const int*>(smem + FA_MASK + (blk & (FA_NST - 1)) * 256);
        float mx0 = -1e30f, mx1 = -1e30f;
#pragma unroll
        for (int t = 0; t < 8; t++) {
            int c0 = t * 8 + (lane & 3) * 2;
            float k0m = (mrow[c0] == 0) ? -1e30f : 0.f;
            float k1m = (mrow[c0 + 1] == 0) ? -1e30f : 0.f;
            S[t][0] = S[t][0] * FA_SCL + k0m;
            S[t][1] = S[t][1] * FA_SCL + k1m;
            S[t][2] = S[t][2] * FA_SCL + k0m;
            S[t][3] = S[t][3] * FA_SCL + k1m;
            mx0 = fmaxf(mx0, fmaxf(S[t][0], S[t][1]));
            mx1 = fmaxf(mx1, fmaxf(S[t][2], S[t][3]));
        }
#pragma unroll
        for (int off = 1; off <= 2; off <<= 1) {
            mx0 = fmaxf(mx0, __shfl_xor_sync(0xffffffffu, mx0, off));
            mx1 = fmaxf(mx1, __shfl_xor_sync(0xffffffffu, mx1, off));
        }
        float mn0 = fmaxf(m0, mx0), mn1 = fmaxf(m1, mx1);
        float al0 = ex2(m0 - mn0), al1 = ex2(m1 - mn1);
        m0 = mn0; m1 = mn1;
        float s0 = 0.f, s1 = 0.f;
#pragma unroll
        for (int t = 0; t < 8; t++) {
            S[t][0] = ex2(S[t][0] - mn0);
            S[t][1] = ex2(S[t][1] - mn0);
            S[t][2] = ex2(S[t][2] - mn1);
            S[t][3] = ex2(S[t][3] - mn1);
            s0 += S[t][0] + S[t][1];
            s1 += S[t][2] + S[t][3];
        }
#pragma unroll
        for (int off = 1; off <= 2; off <<= 1) {
            s0 += __shfl_xor_sync(0xffffffffu, s0, off);
            s1 += __shfl_xor_sync(0xffffffffu, s1, off);
        }
        l0 = l0 * al0 + s0;
        l1 = l1 * al1 + s1;
#pragma unroll
        for (int t = 0; t < 8; t++) {
            O[t][0] *= al0; O[t][1] *= al0;
            O[t][2] *= al1; O[t][3] *= al1;
        }

        // ---- pack P into fp16 A-fragments ----
        uint32_t ph[4][4];
#pragma unroll
        for (int s = 0; s < 4; s++) {
#pragma unroll
            for (int half_i = 0; half_i < 2; half_i++) {
#pragma unroll
                for (int rr = 0; rr < 2; rr++) {
                    float p0 = S[2 * s + half_i][rr * 2 + 0];
                    float p1 = S[2 * s + half_i][rr * 2 + 1];
                    __half2 vh = __floats2half2_rn(p0, p1);
                    ph[s][half_i * 2 + rr] = *reinterpret_cast<uint32_t*>(&vh);
                }
            }
        }

        // ---- O += P V ----
#pragma unroll
        for (int s = 0; s < 4; s++) {
            uint32_t vh[4][4];
#pragma unroll
            for (int np = 0; np < 4; np++) {
                uint32_t base = (uint32_t)((16 * s + v_row) * FA_RS) + np * 32 + v_off;
                ldsm_x4_t(vh[np][0], vh[np][1], vh[np][2], vh[np][3], sb + FA_ARR + base);
            }
#pragma unroll
            for (int np = 0; np < 4; np++) {
                mma_f16(O[2 * np],     ph[s], &vh[np][0]);
                mma_f16(O[2 * np + 1], ph[s], &vh[np][2]);
            }
        }
    }

    // ---- normalize, write ctx [B][N][C] fp16 ----
    const float inv0 = 1.0f / l0, inv1 = 1.0f / l1;
    const int r0 = q0 + wid * 16 + (lane >> 2);
    __half2* c2 = reinterpret_cast<__half2*>(g_c);
#pragma unroll
    for (int t = 0; t < 8; t++) {
        int d = t * 8 + (lane & 3) * 2;
        size_t di0 = (((size_t)(b * NTOK + r0) * CDIM) + h * 64 + d) >> 1;
        size_t di1 = (((size_t)(b * NTOK + r0 + 8) * CDIM) + h * 64 + d) >> 1;
        c2[di0] = __floats2half2_rn(O[t][0] * inv0, O[t][1] * inv0);
        c2[di1] = __floats2half2_rn(O[t][2] * inv1, O[t][3] * inv1);
    }
}

// ---------------- launch ----------------
extern "C" void kernel_launch(void* const* d_in, const int* in_sizes, int n_in,
                              void* d_out, int out_size)
{
    (void)in_sizes; (void)n_in; (void)out_size;
    const float* x    = (const float*)d_in[0];
    const int*   mask = (const int*)d_in[1];
    const float* Wqkv = (const float*)d_in[2];
    const float* bqkv = (const float*)d_in[3];
    const float* Aqkv = (const float*)d_in[4];
    const float* Bqkv = (const float*)d_in[5];
    const float* Wp   = (const float*)d_in[6];
    const float* bp   = (const float*)d_in[7];
    const float* Ap   = (const float*)d_in[8];
    const float* Bp   = (const float*)d_in[9];
    float* out = (float*)d_out;

    fuse_qkv_kernel<<<(QKVC * CDIM + 255) / 256, 256>>>(Wqkv, Bqkv, Aqkv);
    fuse_p_kernel<<<(CDIM * CDIM + 255) / 256, 256>>>(Wp, Bp, Ap);
    cvt_x_kernel<<<(MROWS * CDIM + 255) / 256, 256>>>(x);

    cudaFuncSetAttribute(mma_gemm_qkv, cudaFuncAttributeMaxDynamicSharedMemorySize, GM_SMEM);
    mma_gemm_qkv<<<dim3(QKVC / 128, MROWS / 128), 256, GM_SMEM>>>(bqkv);

    cudaFuncSetAttribute(flash_mma_kernel, cudaFuncAttributeMaxDynamicSharedMemorySize, FA_SMEM);
    flash_mma_kernel<<<dim3(NTOK / 128, HEADS, BATCH), 256, FA_SMEM>>>(mask);

    cudaFuncSetAttribute(mma_gemm_proj, cudaFuncAttributeMaxDynamicSharedMemorySize, GM_SMEM);
    mma_gemm_proj<<<dim3(CDIM / 128, MROWS / 128), 256, GM_SMEM>>>(bp, out);
}

// round 14
// speedup vs baseline: 3.1784x; 1.2248x over previous
#include <cuda_runtime.h>
#include <cuda_fp16.h>
#include <cstdint>

// ---------------- problem constants ----------------
constexpr int BATCH = 2;
constexpr int NTOK  = 2048;
constexpr int CDIM  = 1024;
constexpr int HEADS = 16;
constexpr int MROWS = BATCH * NTOK;     // 4096
constexpr int QKVC  = 3 * CDIM;         // 3072

// ---------------- scratch (device globals, no allocation) ----------------
__device__ __half g_x[MROWS * CDIM];
__device__ __half g_Wq[QKVC * CDIM];
__device__ __half g_Wp[CDIM * CDIM];
__device__ __half g_q[MROWS * CDIM];
__device__ __half g_k[MROWS * CDIM];
__device__ __half g_v[MROWS * CDIM];
__device__ __half g_kc[MROWS * CDIM];   // compacted K
__device__ __half g_vc[MROWS * CDIM];   // compacted V
__device__ __half g_c[MROWS * CDIM];
__device__ int    g_idx[BATCH][NTOK];
__device__ int    g_nvalid[BATCH];

// ---------------- helpers ----------------
__device__ __forceinline__ uint32_t smem_u32(const void* p)
{
    uint32_t a;
    asm("{ .reg .u64 t; cvta.to.shared.u64 t, %1; cvt.u32.u64 %0, t; }" : "=r"(a) : "l"(p));
    return a;
}

__device__ __forceinline__ void cp_async16(uint32_t dst, const void* src)
{
    asm volatile("cp.async.cg.shared.global [%0], [%1], 16;" :: "r"(dst), "l"(src));
}

__device__ __forceinline__ void ldsm_x4(uint32_t& r0, uint32_t& r1, uint32_t& r2, uint32_t& r3,
                                        uint32_t addr)
{
    asm volatile("ldmatrix.sync.aligned.m8n8.x4.shared.b16 {%0,%1,%2,%3}, [%4];"
                 : "=r"(r0), "=r"(r1), "=r"(r2), "=r"(r3) : "r"(addr));
}

__device__ __forceinline__ void ldsm_x4_t(uint32_t& r0, uint32_t& r1, uint32_t& r2, uint32_t& r3,
                                          uint32_t addr)
{
    asm volatile("ldmatrix.sync.aligned.m8n8.x4.trans.shared.b16 {%0,%1,%2,%3}, [%4];"
                 : "=r"(r0), "=r"(r1), "=r"(r2), "=r"(r3) : "r"(addr));
}

__device__ __forceinline__ void mma_f16(float* c, const uint32_t* a, const uint32_t* b)
{
    asm volatile("mma.sync.aligned.m16n8k16.row.col.f32.f16.f16.f32 "
                 "{%0,%1,%2,%3}, {%4,%5,%6,%7}, {%8,%9}, {%0,%1,%2,%3};"
                 : "+f"(c[0]), "+f"(c[1]), "+f"(c[2]), "+f"(c[3])
                 : "r"(a[0]), "r"(a[1]), "r"(a[2]), "r"(a[3]), "r"(b[0]), "r"(b[1]));
}

__device__ __forceinline__ float ex2(float x)
{
    float r;
    asm("ex2.approx.ftz.f32 %0, %1;" : "=f"(r) : "f"(x));
    return r;
}

// ---------------- conversion kernel ----------------
__global__ void cvt_x_kernel(const float* __restrict__ x)
{
    int i = blockIdx.x * blockDim.x + threadIdx.x;
    if (i < MROWS * CDIM) g_x[i] = __float2half_rn(x[i]);
}

// ---------------- weight fusion: Weff = W + 2 * B @ A ----------------
__device__ __forceinline__ void fuse_body(const float* __restrict__ W,
                                          const float* __restrict__ Bm,
                                          const float* __restrict__ A,
                                          __half* __restrict__ Wh, int total)
{
    int idx = blockIdx.x * blockDim.x + threadIdx.x;
    if (idx >= total) return;
    int i = idx >> 10;
    int j = idx & 1023;
    float s = 0.f;
#pragma unroll
    for (int r = 0; r < 16; r++) s += Bm[i * 16 + r] * A[r * CDIM + j];
    Wh[idx] = __float2half_rn(W[idx] + 2.0f * s);
}

__global__ void fuse_qkv_kernel(const float* __restrict__ W, const float* __restrict__ Bm,
                                const float* __restrict__ A)
{
    fuse_body(W, Bm, A, g_Wq, QKVC * CDIM);
}

__global__ void fuse_p_kernel(const float* __restrict__ W, const float* __restrict__ Bm,
                              const float* __restrict__ A)
{
    fuse_body(W, Bm, A, g_Wp, CDIM * CDIM);
}

// ---------------- mask compaction: ordered indices of valid keys per batch ---------
__global__ void scan_mask_kernel(const int* __restrict__ mask)
{
    int b = blockIdx.x;
    int t = threadIdx.x;            // 256 threads, 8 elements each
    const int* m = mask + b * NTOK;
    int loc[8];
    int c = 0;
#pragma unroll
    for (int i = 0; i < 8; i++) {
        int p = t * 8 + i;
        if (m[p] != 0) loc[c++] = p;
    }
    __shared__ int cnts[256];
    cnts[t] = c;
    __syncthreads();
    for (int off = 1; off < 256; off <<= 1) {
        int v = (t >= off) ? cnts[t - off] : 0;
        __syncthreads();
        cnts[t] += v;
        __syncthreads();
    }
    int start = cnts[t] - c;
    for (int i = 0; i < c; i++) g_idx[b][start + i] = loc[i];
    if (t == 255) g_nvalid[b] = cnts[255];
}

// gather valid K/V rows into compacted arrays [B][H][j][64]
__global__ void gather_kv_kernel()
{
    int b = blockIdx.z, h = blockIdx.y;
    int jr = blockIdx.x * 16 + (threadIdx.x >> 3);   // compacted row
    int ch = threadIdx.x & 7;                        // 16B chunk
    if (jr >= g_nvalid[b]) return;
    int src = g_idx[b][jr];
    size_t base = (size_t)(b * HEADS + h) * NTOK;
    reinterpret_cast<uint4*>(g_kc + (base + jr) * 64)[ch] =
        reinterpret_cast<const uint4*>(g_k + (base + src) * 64)[ch];
    reinterpret_cast<uint4*>(g_vc + (base + jr) * 64)[ch] =
        reinterpret_cast<const uint4*>(g_v + (base + src) * 64)[ch];
}

// ---------------- HMMA GEMM (128x128 tile, 8 warps, pure fp16) ----------------------
constexpr int GM_RS    = 80;
constexpr int GM_ARR   = 128 * GM_RS;        // 10240
constexpr int GM_STAGE = 2 * GM_ARR;         // 20480 (A|B)
constexpr int GM_SMEM  = 2 * GM_STAGE;       // 40960
constexpr int KCH      = 32;
constexpr int NCHUNK   = 1024 / KCH;         // 32

__device__ __forceinline__ void gm_load_chunk(uint32_t su, int tid,
                                              const __half* const* srcs, int c)
{
    uint32_t stage = su + (uint32_t)(c & 1) * GM_STAGE;
    int k0 = c * KCH;
#pragma unroll
    for (int i = 0; i < 4; i++) {
        int g = i * 256 + tid;
        int t = g >> 9;
        int e = g & 511;
        int r = e >> 2;
        int c16 = e & 3;
        cp_async16(stage + t * GM_ARR + r * GM_RS + c16 * 16,
                   srcs[t] + (size_t)r * 1024 + k0 + c16 * 8);
    }
    asm volatile("cp.async.commit_group;");
}

template <bool QKV_SPLIT_OUT>
__device__ __forceinline__ void mma_gemm_body(const __half* __restrict__ Af,
                                              const __half* __restrict__ Bf,
                                              const float* __restrict__ bias,
                                              float* __restrict__ C, int Nc)
{
    extern __shared__ char smem[];
    const uint32_t su = smem_u32(smem);
    const int tid = threadIdx.x;
    const int wid = tid >> 5, lane = tid & 31;
    const int warp_m = wid >> 2, warp_n = wid & 3;
    const int row0 = blockIdx.y * 128;
    const int col0 = blockIdx.x * 128;

    const __half* srcs[2] = { Af + (size_t)row0 * 1024, Bf + (size_t)col0 * 1024 };

    float acc[4][4][4];
#pragma unroll
    for (int mt = 0; mt < 4; mt++)
#pragma unroll
        for (int nt = 0; nt < 4; nt++)
#pragma unroll
            for (int f = 0; f < 4; f++) acc[mt][nt][f] = 0.f;

    gm_load_chunk(su, tid, srcs, 0);

    const int a_row = warp_m * 64 + (lane & 15);
    const int a_kb  = (lane >> 4) << 4;
    const int b_row = warp_n * 32 + ((lane & 7) | ((lane & 16) >> 1));
    const int b_kb  = (lane & 8) << 1;

    for (int c = 0; c < NCHUNK; c++) {
        if (c + 1 < NCHUNK) {
            __syncthreads();
            gm_load_chunk(su, tid, srcs, c + 1);
            asm volatile("cp.async.wait_group 1;" ::: "memory");
        } else {
            asm volatile("cp.async.wait_group 0;" ::: "memory");
        }
        __syncthreads();

        const uint32_t stage = su + (uint32_t)(c & 1) * GM_STAGE;
#pragma unroll
        for (int ks = 0; ks < 2; ks++) {
            const uint32_t koff = ks * 32;

            uint32_t ah[4][4];
#pragma unroll
            for (int mt = 0; mt < 4; mt++) {
                uint32_t base = (uint32_t)((a_row + mt * 16) * GM_RS + a_kb + koff);
                ldsm_x4(ah[mt][0], ah[mt][1], ah[mt][2], ah[mt][3], stage + base);
            }
            uint32_t bh[4][2];
#pragma unroll
            for (int np = 0; np < 2; np++) {
                uint32_t base = (uint32_t)((b_row + np * 16) * GM_RS + b_kb + koff);
                uint32_t r0, r1, r2, r3;
                ldsm_x4(r0, r1, r2, r3, stage + GM_ARR + base);
                bh[np * 2][0] = r0; bh[np * 2][1] = r1;
                bh[np * 2 + 1][0] = r2; bh[np * 2 + 1][1] = r3;
            }
#pragma unroll
            for (int mt = 0; mt < 4; mt++)
#pragma unroll
                for (int nt = 0; nt < 4; nt++)
                    mma_f16(acc[mt][nt], ah[mt], bh[nt]);
        }
    }

    if (!QKV_SPLIT_OUT) {
#pragma unroll
        for (int mt = 0; mt < 4; mt++) {
            int rg = row0 + warp_m * 64 + mt * 16 + (lane >> 2);
#pragma unroll
            for (int nt = 0; nt < 4; nt++) {
                int cg = col0 + warp_n * 32 + nt * 8 + (lane & 3) * 2;
                float b0 = bias[cg], b1 = bias[cg + 1];
                float2 v0 = make_float2(acc[mt][nt][0] + b0, acc[mt][nt][1] + b1);
                float2 v1 = make_float2(acc[mt][nt][2] + b0, acc[mt][nt][3] + b1);
                *reinterpret_cast<float2*>(&C[(size_t)rg * Nc + cg]) = v0;
                *reinterpret_cast<float2*>(&C[(size_t)(rg + 8) * Nc + cg]) = v1;
            }
        }
    } else {
        __half2* q2 = reinterpret_cast<__half2*>(g_q);
        __half2* k2 = reinterpret_cast<__half2*>(g_k);
        __half2* v2 = reinterpret_cast<__half2*>(g_v);
#pragma unroll
        for (int nt = 0; nt < 4; nt++) {
            int cg = col0 + warp_n * 32 + nt * 8 + (lane & 3) * 2;
            int which = cg >> 10;      // 0=q 1=k 2=v
            int rem = cg & 1023;
            int h = rem >> 6;
            int d = rem & 63;
            float b0 = bias[cg], b1 = bias[cg + 1];
            __half2* dst = (which == 0) ? q2 : (which == 1) ? k2 : v2;
#pragma unroll
            for (int mt = 0; mt < 4; mt++) {
                int rbase = row0 + warp_m * 64 + mt * 16 + (lane >> 2);
#pragma unroll
                for (int half_i = 0; half_i < 2; half_i++) {
                    int r = rbase + half_i * 8;
                    int bb = r >> 11, n = r & 2047;
                    size_t di = (((size_t)((bb << 4) + h) * 2048 + n) * 64 + d) >> 1;
                    float v0 = acc[mt][nt][half_i * 2 + 0] + b0;
                    float v1 = acc[mt][nt][half_i * 2 + 1] + b1;
                    dst[di] = __floats2half2_rn(v0, v1);
                }
            }
        }
    }
}

__global__ void __launch_bounds__(256, 2)
mma_gemm_qkv(const float* __restrict__ bias)
{
    mma_gemm_body<true>(g_x, g_Wq, bias, nullptr, QKVC);
}

__global__ void __launch_bounds__(256, 2)
mma_gemm_proj(const float* __restrict__ bias, float* __restrict__ out)
{
    mma_gemm_body<false>(g_c, g_Wp, bias, out, CDIM);
}

// ---------------- HMMA flash attention on COMPACTED keys ----------------------------
// BQ=128, BK=64, d=64, 8 warps, pure fp16, runtime block count, no smem mask.
constexpr int FA_RS    = 144;
constexpr int FA_ARR   = 64 * FA_RS;        // 9216
constexpr int FA_STAGE = 2 * FA_ARR;        // 18432 (K|V)
constexpr int FA_NST   = 4;
constexpr int FA_SMEM  = FA_NST * FA_STAGE; // 73728
constexpr float FA_SCL = 0.18033688f;       // 0.125 * log2(e)

__device__ __forceinline__ void fa_load_stage(uint32_t su, int tid,
                                              const __half* K, const __half* V, int blk)
{
    const uint32_t sb = su + (uint32_t)(blk & (FA_NST - 1)) * FA_STAGE;
    const size_t off = (size_t)blk * 64 * 64;
    const __half* srcs[2] = { K + off, V + off };
#pragma unroll
    for (int i = 0; i < 4; i++) {
        int g = i * 256 + tid;
        int arr = g >> 9;
        int e = g & 511;
        int r = e >> 3;
        int ch = e & 7;
        cp_async16(sb + arr * FA_ARR + r * FA_RS + ch * 16,
                   srcs[arr] + (size_t)r * 64 + ch * 8);
    }
    asm volatile("cp.async.commit_group;");
}

__global__ void __launch_bounds__(256)
flash_mma_kernel()
{
    extern __shared__ char smem[];
    const uint32_t su = smem_u32(smem);
    const int tid = threadIdx.x;
    const int wid = tid >> 5, lane = tid & 31;
    const int b = blockIdx.z, h = blockIdx.y;
    const int q0 = blockIdx.x * 128;
    const size_t bh = (size_t)(b * HEADS + h);

    const __half* Q = g_q + (bh * NTOK + q0) * 64;
    const __half* K = g_kc + bh * NTOK * 64;
    const __half* V = g_vc + bh * NTOK * 64;
    const int nv = g_nvalid[b];
    const int nblk = (nv + 63) >> 6;

    // stage Q at su, pull to regs, region then reused by K/V stages
#pragma unroll
    for (int i = 0; i < 4; i++) {
        int g = i * 256 + tid;
        int r = g >> 3;
        int ch = g & 7;
        cp_async16(su + r * FA_RS + ch * 16, Q + (size_t)r * 64 + ch * 8);
    }
    asm volatile("cp.async.commit_group;");
    asm volatile("cp.async.wait_group 0;" ::: "memory");
    __syncthreads();

    uint32_t qh[4][4];
    {
        const int ar = wid * 16 + (lane & 15);
        const uint32_t ab = (uint32_t)((lane >> 4) << 4);
#pragma unroll
        for (int ks = 0; ks < 4; ks++) {
            uint32_t base = (uint32_t)(ar * FA_RS) + ab + ks * 32;
            ldsm_x4(qh[ks][0], qh[ks][1], qh[ks][2], qh[ks][3], su + base);
        }
    }
    __syncthreads();

    float O[8][4];
#pragma unroll
    for (int t = 0; t < 8; t++)
#pragma unroll
        for (int f = 0; f < 4; f++) O[t][f] = 0.f;
    float m0 = -1e30f, m1 = -1e30f, l0 = 0.f, l1 = 0.f;

    // prologue: 3 stages (arrays are full-size; beyond-nblk rows are unused garbage)
    fa_load_stage(su, tid, K, V, 0);
    fa_load_stage(su, tid, K, V, 1);
    fa_load_stage(su, tid, K, V, 2);

    const int kb_row = (lane & 7) | ((lane & 16) >> 1);
    const uint32_t kb_off = (uint32_t)((lane & 8) << 1);
    const int v_row = lane & 15;
    const uint32_t v_off = (uint32_t)(((lane & 16) >> 4) * 16);

    for (int blk = 0; blk < nblk; blk++) {
        // uniform: exactly 2 newer groups committed at every wait
        asm volatile("cp.async.wait_group 2;" ::: "memory");
        __syncthreads();
        if (blk + 3 < nblk) fa_load_stage(su, tid, K, V, blk + 3);
        else asm volatile("cp.async.commit_group;");   // empty group keeps count uniform

        const uint32_t sb = su + (uint32_t)(blk & (FA_NST - 1)) * FA_STAGE;

        // ---- S = Q K^T ----
        float S[8][4];
#pragma unroll
        for (int t = 0; t < 8; t++)
#pragma unroll
            for (int f = 0; f < 4; f++) S[t][f] = 0.f;

#pragma unroll
        for (int ks = 0; ks < 4; ks++) {
            uint32_t kh[4][4];
#pragma unroll
            for (int np = 0; np < 4; np++) {
                uint32_t base = (uint32_t)((np * 16 + kb_row) * FA_RS) + kb_off + ks * 32;
                ldsm_x4(kh[np][0], kh[np][1], kh[np][2], kh[np][3], sb + base);
            }
#pragma unroll
            for (int np = 0; np < 4; np++) {
                mma_f16(S[2 * np],     qh[ks], &kh[np][0]);
                mma_f16(S[2 * np + 1], qh[ks], &kh[np][2]);
            }
        }

        // ---- tail mask (register compare, no smem) + online softmax (base-2) ----
        const int jbase = blk * 64;
        float mx0 = -1e30f, mx1 = -1e30f;
#pragma unroll
        for (int t = 0; t < 8; t++) {
            int c0 = t * 8 + (lane & 3) * 2;
            float k0m = (jbase + c0     < nv) ? 0.f : -1e30f;
            float k1m = (jbase + c0 + 1 < nv) ? 0.f : -1e30f;
            S[t][0] = S[t][0] * FA_SCL + k0m;
            S[t][1] = S[t][1] * FA_SCL + k1m;
            S[t][2] = S[t][2] * FA_SCL + k0m;
            S[t][3] = S[t][3] * FA_SCL + k1m;
            mx0 = fmaxf(mx0, fmaxf(S[t][0], S[t][1]));
            mx1 = fmaxf(mx1, fmaxf(S[t][2], S[t][3]));
        }
#pragma unroll
        for (int off = 1; off <= 2; off <<= 1) {
            mx0 = fmaxf(mx0, __shfl_xor_sync(0xffffffffu, mx0, off));
            mx1 = fmaxf(mx1, __shfl_xor_sync(0xffffffffu, mx1, off));
        }
        float mn0 = fmaxf(m0, mx0), mn1 = fmaxf(m1, mx1);
        float al0 = ex2(m0 - mn0), al1 = ex2(m1 - mn1);
        m0 = mn0; m1 = mn1;
        float s0 = 0.f, s1 = 0.f;
#pragma unroll
        for (int t = 0; t < 8; t++) {
            S[t][0] = ex2(S[t][0] - mn0);
            S[t][1] = ex2(S[t][1] - mn0);
            S[t][2] = ex2(S[t][2] - mn1);
            S[t][3] = ex2(S[t][3] - mn1);
            s0 += S[t][0] + S[t][1];
            s1 += S[t][2] + S[t][3];
        }
#pragma unroll
        for (int off = 1; off <= 2; off <<= 1) {
            s0 += __shfl_xor_sync(0xffffffffu, s0, off);
            s1 += __shfl_xor_sync(0xffffffffu, s1, off);
        }
        l0 = l0 * al0 + s0;
        l1 = l1 * al1 + s1;
#pragma unroll
        for (int t = 0; t < 8; t++) {
            O[t][0] *= al0; O[t][1] *= al0;
            O[t][2] *= al1; O[t][3] *= al1;
        }

        // ---- pack P into fp16 A-fragments ----
        uint32_t ph[4][4];
#pragma unroll
        for (int s = 0; s < 4; s++) {
#pragma unroll
            for (int half_i = 0; half_i < 2; half_i++) {
#pragma unroll
                for (int rr = 0; rr < 2; rr++) {
                    float p0 = S[2 * s + half_i][rr * 2 + 0];
                    float p1 = S[2 * s + half_i][rr * 2 + 1];
                    __half2 vh = __floats2half2_rn(p0, p1);
                    ph[s][half_i * 2 + rr] = *reinterpret_cast<uint32_t*>(&vh);
                }
            }
        }

        // ---- O += P V ----
#pragma unroll
        for (int s = 0; s < 4; s++) {
            uint32_t vh[4][4];
#pragma unroll
            for (int np = 0; np < 4; np++) {
                uint32_t base = (uint32_t)((16 * s + v_row) * FA_RS) + np * 32 + v_off;
                ldsm_x4_t(vh[np][0], vh[np][1], vh[np][2], vh[np][3], sb + FA_ARR + base);
            }
#pragma unroll
            for (int np = 0; np < 4; np++) {
                mma_f16(O[2 * np],     ph[s], &vh[np][0]);
                mma_f16(O[2 * np + 1], ph[s], &vh[np][2]);
            }
        }
    }

    // ---- normalize, write ctx [B][N][C] fp16 ----
    const float inv0 = 1.0f / l0, inv1 = 1.0f / l1;
    const int r0 = q0 + wid * 16 + (lane >> 2);
    __half2* c2 = reinterpret_cast<__half2*>(g_c);
#pragma unroll
    for (int t = 0; t < 8; t++) {
        int d = t * 8 + (lane & 3) * 2;
        size_t di0 = (((size_t)(b * NTOK + r0) * CDIM) + h * 64 + d) >> 1;
        size_t di1 = (((size_t)(b * NTOK + r0 + 8) * CDIM) + h * 64 + d) >> 1;
        c2[di0] = __floats2half2_rn(O[t][0] * inv0, O[t][1] * inv0);
        c2[di1] = __floats2half2_rn(O[t][2] * inv1, O[t][3] * inv1);
    }
}

// ---------------- launch ----------------
extern "C" void kernel_launch(void* const* d_in, const int* in_sizes, int n_in,
                              void* d_out, int out_size)
{
    (void)in_sizes; (void)n_in; (void)out_size;
    const float* x    = (const float*)d_in[0];
    const int*   mask = (const int*)d_in[1];
    const float* Wqkv = (const float*)d_in[2];
    const float* bqkv = (const float*)d_in[3];
    const float* Aqkv = (const float*)d_in[4];
    const float* Bqkv = (const float*)d_in[5];
    const float* Wp   = (const float*)d_in[6];
    const float* bp   = (const float*)d_in[7];
    const float* Ap   = (const float*)d_in[8];
    const float* Bp   = (const float*)d_in[9];
    float* out = (float*)d_out;

    fuse_qkv_kernel<<<(QKVC * CDIM + 255) / 256, 256>>>(Wqkv, Bqkv, Aqkv);
    fuse_p_kernel<<<(CDIM * CDIM + 255) / 256, 256>>>(Wp, Bp, Ap);
    cvt_x_kernel<<<(MROWS * CDIM + 255) / 256, 256>>>(x);
    scan_mask_kernel<<<BATCH, 256>>>(mask);

    cudaFuncSetAttribute(mma_gemm_qkv, cudaFuncAttributeMaxDynamicSharedMemorySize, GM_SMEM);
    mma_gemm_qkv<<<dim3(QKVC / 128, MROWS / 128), 256, GM_SMEM>>>(bqkv);

    gather_kv_kernel<<<dim3(NTOK / 16, HEADS, BATCH), 128>>>();

    cudaFuncSetAttribute(flash_mma_kernel, cudaFuncAttributeMaxDynamicSharedMemorySize, FA_SMEM);
    flash_mma_kernel<<<dim3(NTOK / 128, HEADS, BATCH), 256, FA_SMEM>>>();

    cudaFuncSetAttribute(mma_gemm_proj, cudaFuncAttributeMaxDynamicSharedMemorySize, GM_SMEM);
    mma_gemm_proj<<<dim3(CDIM / 128, MROWS / 128), 256, GM_SMEM>>>(bp, out);
}

// round 15
// speedup vs baseline: 3.5928x; 1.1304x over previous
#include <cuda_runtime.h>
#include <cuda_fp16.h>
#include <cstdint>

// ---------------- problem constants ----------------
constexpr int BATCH = 2;
constexpr int NTOK  = 2048;
constexpr int CDIM  = 1024;
constexpr int HEADS = 16;
constexpr int MROWS = BATCH * NTOK;     // 4096
constexpr int QKVC  = 3 * CDIM;         // 3072

// ---------------- scratch (device globals, no allocation) ----------------
__device__ __half g_x[MROWS * CDIM];
__device__ __half g_xc[MROWS * CDIM];   // compacted valid x rows (zero-init; tail rows stay 0)
__device__ __half g_Wq[QKVC * CDIM];
__device__ __half g_Wp[CDIM * CDIM];
__device__ __half g_q[MROWS * CDIM];
__device__ __half g_kc[MROWS * CDIM];   // compacted K (written directly by kv GEMM)
__device__ __half g_vc[MROWS * CDIM];   // compacted V
__device__ __half g_c[MROWS * CDIM];
__device__ int    g_idx[BATCH][NTOK];
__device__ int    g_nvalid[BATCH];

// ---------------- helpers ----------------
__device__ __forceinline__ uint32_t smem_u32(const void* p)
{
    uint32_t a;
    asm("{ .reg .u64 t; cvta.to.shared.u64 t, %1; cvt.u32.u64 %0, t; }" : "=r"(a) : "l"(p));
    return a;
}

__device__ __forceinline__ void cp_async16(uint32_t dst, const void* src)
{
    asm volatile("cp.async.cg.shared.global [%0], [%1], 16;" :: "r"(dst), "l"(src));
}

__device__ __forceinline__ void ldsm_x4(uint32_t& r0, uint32_t& r1, uint32_t& r2, uint32_t& r3,
                                        uint32_t addr)
{
    asm volatile("ldmatrix.sync.aligned.m8n8.x4.shared.b16 {%0,%1,%2,%3}, [%4];"
                 : "=r"(r0), "=r"(r1), "=r"(r2), "=r"(r3) : "r"(addr));
}

__device__ __forceinline__ void ldsm_x4_t(uint32_t& r0, uint32_t& r1, uint32_t& r2, uint32_t& r3,
                                          uint32_t addr)
{
    asm volatile("ldmatrix.sync.aligned.m8n8.x4.trans.shared.b16 {%0,%1,%2,%3}, [%4];"
                 : "=r"(r0), "=r"(r1), "=r"(r2), "=r"(r3) : "r"(addr));
}

__device__ __forceinline__ void mma_f16(float* c, const uint32_t* a, const uint32_t* b)
{
    asm volatile("mma.sync.aligned.m16n8k16.row.col.f32.f16.f16.f32 "
                 "{%0,%1,%2,%3}, {%4,%5,%6,%7}, {%8,%9}, {%0,%1,%2,%3};"
                 : "+f"(c[0]), "+f"(c[1]), "+f"(c[2]), "+f"(c[3])
                 : "r"(a[0]), "r"(a[1]), "r"(a[2]), "r"(a[3]), "r"(b[0]), "r"(b[1]));
}

__device__ __forceinline__ float ex2(float x)
{
    float r;
    asm("ex2.approx.ftz.f32 %0, %1;" : "=f"(r) : "f"(x));
    return r;
}

// ---------------- conversion kernel ----------------
__global__ void cvt_x_kernel(const float* __restrict__ x)
{
    int i = blockIdx.x * blockDim.x + threadIdx.x;
    if (i < MROWS * CDIM) g_x[i] = __float2half_rn(x[i]);
}

// ---------------- weight fusion: Weff = W + 2 * B @ A ----------------
__device__ __forceinline__ void fuse_body(const float* __restrict__ W,
                                          const float* __restrict__ Bm,
                                          const float* __restrict__ A,
                                          __half* __restrict__ Wh, int total)
{
    int idx = blockIdx.x * blockDim.x + threadIdx.x;
    if (idx >= total) return;
    int i = idx >> 10;
    int j = idx & 1023;
    float s = 0.f;
#pragma unroll
    for (int r = 0; r < 16; r++) s += Bm[i * 16 + r] * A[r * CDIM + j];
    Wh[idx] = __float2half_rn(W[idx] + 2.0f * s);
}

__global__ void fuse_qkv_kernel(const float* __restrict__ W, const float* __restrict__ Bm,
                                const float* __restrict__ A)
{
    fuse_body(W, Bm, A, g_Wq, QKVC * CDIM);
}

__global__ void fuse_p_kernel(const float* __restrict__ W, const float* __restrict__ Bm,
                              const float* __restrict__ A)
{
    fuse_body(W, Bm, A, g_Wp, CDIM * CDIM);
}

// ---------------- mask compaction: ordered indices of valid keys per batch ---------
__global__ void scan_mask_kernel(const int* __restrict__ mask)
{
    int b = blockIdx.x;
    int t = threadIdx.x;            // 256 threads, 8 elements each
    const int* m = mask + b * NTOK;
    int loc[8];
    int c = 0;
#pragma unroll
    for (int i = 0; i < 8; i++) {
        int p = t * 8 + i;
        if (m[p] != 0) loc[c++] = p;
    }
    __shared__ int cnts[256];
    cnts[t] = c;
    __syncthreads();
    for (int off = 1; off < 256; off <<= 1) {
        int v = (t >= off) ? cnts[t - off] : 0;
        __syncthreads();
        cnts[t] += v;
        __syncthreads();
    }
    int start = cnts[t] - c;
    for (int i = 0; i < c; i++) g_idx[b][start + i] = loc[i];
    if (t == 255) g_nvalid[b] = cnts[255];
}

// gather valid x rows into g_xc (one block per compacted row; 128 thr x 16B = 2048B)
__global__ void gather_x_kernel()
{
    int b = blockIdx.y;
    int jr = blockIdx.x;
    if (jr >= g_nvalid[b]) return;
    int src = g_idx[b][jr];
    const uint4* s = reinterpret_cast<const uint4*>(g_x + ((size_t)b * NTOK + src) * CDIM);
    uint4* d = reinterpret_cast<uint4*>(g_xc + ((size_t)b * NTOK + jr) * CDIM);
    d[threadIdx.x] = s[threadIdx.x];
}

// ---------------- HMMA GEMM (128x128 tile, 8 warps, pure fp16) ----------------------
// MODE 0 = plain C out (proj); 1 = q epilogue; 2 = compacted k/v epilogue
constexpr int GM_RS    = 80;
constexpr int GM_ARR   = 128 * GM_RS;        // 10240
constexpr int GM_STAGE = 2 * GM_ARR;         // 20480 (A|B)
constexpr int GM_SMEM  = 2 * GM_STAGE;       // 40960
constexpr int KCH      = 32;
constexpr int NCHUNK   = 1024 / KCH;         // 32

__device__ __forceinline__ void gm_load_chunk(uint32_t su, int tid,
                                              const __half* const* srcs, int c)
{
    uint32_t stage = su + (uint32_t)(c & 1) * GM_STAGE;
    int k0 = c * KCH;
#pragma unroll
    for (int i = 0; i < 4; i++) {
        int g = i * 256 + tid;
        int t = g >> 9;
        int e = g & 511;
        int r = e >> 2;
        int c16 = e & 3;
        cp_async16(stage + t * GM_ARR + r * GM_RS + c16 * 16,
                   srcs[t] + (size_t)r * 1024 + k0 + c16 * 8);
    }
    asm volatile("cp.async.commit_group;");
}

template <int MODE>
__device__ __forceinline__ void mma_gemm_body(const __half* __restrict__ Atile,
                                              const __half* __restrict__ Btile,
                                              const float* __restrict__ bias,
                                              float* __restrict__ C, int Nc,
                                              int row0, int col0, int b, int jr0)
{
    extern __shared__ char smem[];
    const uint32_t su = smem_u32(smem);
    const int tid = threadIdx.x;
    const int wid = tid >> 5, lane = tid & 31;
    const int warp_m = wid >> 2, warp_n = wid & 3;

    const __half* srcs[2] = { Atile, Btile };

    float acc[4][4][4];
#pragma unroll
    for (int mt = 0; mt < 4; mt++)
#pragma unroll
        for (int nt = 0; nt < 4; nt++)
#pragma unroll
            for (int f = 0; f < 4; f++) acc[mt][nt][f] = 0.f;

    gm_load_chunk(su, tid, srcs, 0);

    const int a_row = warp_m * 64 + (lane & 15);
    const int a_kb  = (lane >> 4) << 4;
    const int b_row = warp_n * 32 + ((lane & 7) | ((lane & 16) >> 1));
    const int b_kb  = (lane & 8) << 1;

    for (int c = 0; c < NCHUNK; c++) {
        if (c + 1 < NCHUNK) {
            __syncthreads();
            gm_load_chunk(su, tid, srcs, c + 1);
            asm volatile("cp.async.wait_group 1;" ::: "memory");
        } else {
            asm volatile("cp.async.wait_group 0;" ::: "memory");
        }
        __syncthreads();

        const uint32_t stage = su + (uint32_t)(c & 1) * GM_STAGE;
#pragma unroll
        for (int ks = 0; ks < 2; ks++) {
            const uint32_t koff = ks * 32;

            uint32_t ah[4][4];
#pragma unroll
            for (int mt = 0; mt < 4; mt++) {
                uint32_t base = (uint32_t)((a_row + mt * 16) * GM_RS + a_kb + koff);
                ldsm_x4(ah[mt][0], ah[mt][1], ah[mt][2], ah[mt][3], stage + base);
            }
            uint32_t bh[4][2];
#pragma unroll
            for (int np = 0; np < 2; np++) {
                uint32_t base = (uint32_t)((b_row + np * 16) * GM_RS + b_kb + koff);
                uint32_t r0, r1, r2, r3;
                ldsm_x4(r0, r1, r2, r3, stage + GM_ARR + base);
                bh[np * 2][0] = r0; bh[np * 2][1] = r1;
                bh[np * 2 + 1][0] = r2; bh[np * 2 + 1][1] = r3;
            }
#pragma unroll
            for (int mt = 0; mt < 4; mt++)
#pragma unroll
                for (int nt = 0; nt < 4; nt++)
                    mma_f16(acc[mt][nt], ah[mt], bh[nt]);
        }
    }

    if (MODE == 0) {
#pragma unroll
        for (int mt = 0; mt < 4; mt++) {
            int rg = row0 + warp_m * 64 + mt * 16 + (lane >> 2);
#pragma unroll
            for (int nt = 0; nt < 4; nt++) {
                int cg = col0 + warp_n * 32 + nt * 8 + (lane & 3) * 2;
                float b0 = bias[cg], b1 = bias[cg + 1];
                float2 v0 = make_float2(acc[mt][nt][0] + b0, acc[mt][nt][1] + b1);
                float2 v1 = make_float2(acc[mt][nt][2] + b0, acc[mt][nt][3] + b1);
                *reinterpret_cast<float2*>(&C[(size_t)rg * Nc + cg]) = v0;
                *reinterpret_cast<float2*>(&C[(size_t)(rg + 8) * Nc + cg]) = v1;
            }
        }
    } else if (MODE == 1) {
        // q out: row r -> (b,n); col cg -> (h,d); [B][H][N][64]
        __half2* q2 = reinterpret_cast<__half2*>(g_q);
#pragma unroll
        for (int nt = 0; nt < 4; nt++) {
            int cg = col0 + warp_n * 32 + nt * 8 + (lane & 3) * 2;
            int h = cg >> 6;
            int d = cg & 63;
            float b0 = bias[cg], b1 = bias[cg + 1];
#pragma unroll
            for (int mt = 0; mt < 4; mt++) {
                int rbase = row0 + warp_m * 64 + mt * 16 + (lane >> 2);
#pragma unroll
                for (int half_i = 0; half_i < 2; half_i++) {
                    int r = rbase + half_i * 8;
                    int bb = r >> 11, n = r & 2047;
                    size_t di = (((size_t)((bb << 4) + h) * 2048 + n) * 64 + d) >> 1;
                    q2[di] = __floats2half2_rn(acc[mt][nt][half_i * 2 + 0] + b0,
                                               acc[mt][nt][half_i * 2 + 1] + b1);
                }
            }
        }
    } else {
        // compacted k/v out: row = jr0 + local (compacted j); cg -> which/h/d
        __half2* k2 = reinterpret_cast<__half2*>(g_kc);
        __half2* v2 = reinterpret_cast<__half2*>(g_vc);
#pragma unroll
        for (int nt = 0; nt < 4; nt++) {
            int cg = col0 + warp_n * 32 + nt * 8 + (lane & 3) * 2;
            int which = cg >> 10;      // 0=k 1=v
            int rem = cg & 1023;
            int h = rem >> 6;
            int d = rem & 63;
            float b0 = bias[cg], b1 = bias[cg + 1];
            __half2* dst = which ? v2 : k2;
#pragma unroll
            for (int mt = 0; mt < 4; mt++) {
                int jbase = jr0 + warp_m * 64 + mt * 16 + (lane >> 2);
#pragma unroll
                for (int half_i = 0; half_i < 2; half_i++) {
                    int j = jbase + half_i * 8;
                    size_t di = (((size_t)((b << 4) + h) * 2048 + j) * 64 + d) >> 1;
                    dst[di] = __floats2half2_rn(acc[mt][nt][half_i * 2 + 0] + b0,
                                                acc[mt][nt][half_i * 2 + 1] + b1);
                }
            }
        }
    }
}

__global__ void __launch_bounds__(256, 2)
mma_gemm_q(const float* __restrict__ bias)
{
    int row0 = blockIdx.y * 128, col0 = blockIdx.x * 128;
    mma_gemm_body<1>(g_x + (size_t)row0 * 1024, g_Wq + (size_t)col0 * 1024,
                     bias, nullptr, CDIM, row0, col0, 0, 0);
}

__global__ void __launch_bounds__(256, 2)
mma_gemm_kv(const float* __restrict__ bias)
{
    int b = blockIdx.y >> 4;
    int jr0 = (blockIdx.y & 15) * 128;
    if (jr0 >= g_nvalid[b]) return;        // whole-CTA early exit, before any sync
    int col0 = blockIdx.x * 128;
    mma_gemm_body<2>(g_xc + ((size_t)b * NTOK + jr0) * 1024,
                     g_Wq + (size_t)(CDIM + col0) * 1024,
                     bias + CDIM, nullptr, 2 * CDIM, 0, col0, b, jr0);
}

__global__ void __launch_bounds__(256, 2)
mma_gemm_proj(const float* __restrict__ bias, float* __restrict__ out)
{
    int row0 = blockIdx.y * 128, col0 = blockIdx.x * 128;
    mma_gemm_body<0>(g_c + (size_t)row0 * 1024, g_Wp + (size_t)col0 * 1024,
                     bias, out, CDIM, row0, col0, 0, 0);
}

// ---------------- HMMA flash attention on COMPACTED keys ----------------------------
constexpr int FA_RS    = 144;
constexpr int FA_ARR   = 64 * FA_RS;        // 9216
constexpr int FA_STAGE = 2 * FA_ARR;        // 18432 (K|V)
constexpr int FA_NST   = 4;
constexpr int FA_SMEM  = FA_NST * FA_STAGE; // 73728
constexpr float FA_SCL = 0.18033688f;       // 0.125 * log2(e)

__device__ __forceinline__ void fa_load_stage(uint32_t su, int tid,
                                              const __half* K, const __half* V, int blk)
{
    const uint32_t sb = su + (uint32_t)(blk & (FA_NST - 1)) * FA_STAGE;
    const size_t off = (size_t)blk * 64 * 64;
    const __half* srcs[2] = { K + off, V + off };
#pragma unroll
    for (int i = 0; i < 4; i++) {
        int g = i * 256 + tid;
        int arr = g >> 9;
        int e = g & 511;
        int r = e >> 3;
        int ch = e & 7;
        cp_async16(sb + arr * FA_ARR + r * FA_RS + ch * 16,
                   srcs[arr] + (size_t)r * 64 + ch * 8);
    }
    asm volatile("cp.async.commit_group;");
}

__global__ void __launch_bounds__(256)
flash_mma_kernel()
{
    extern __shared__ char smem[];
    const uint32_t su = smem_u32(smem);
    const int tid = threadIdx.x;
    const int wid = tid >> 5, lane = tid & 31;
    const int b = blockIdx.z, h = blockIdx.y;
    const int q0 = blockIdx.x * 128;
    const size_t bh = (size_t)(b * HEADS + h);

    const __half* Q = g_q + (bh * NTOK + q0) * 64;
    const __half* K = g_kc + bh * NTOK * 64;
    const __half* V = g_vc + bh * NTOK * 64;
    const int nv = g_nvalid[b];
    const int nblk = (nv + 63) >> 6;

    // stage Q at su, pull to regs, region then reused by K/V stages
#pragma unroll
    for (int i = 0; i < 4; i++) {
        int g = i * 256 + tid;
        int r = g >> 3;
        int ch = g & 7;
        cp_async16(su + r * FA_RS + ch * 16, Q + (size_t)r * 64 + ch * 8);
    }
    asm volatile("cp.async.commit_group;");
    asm volatile("cp.async.wait_group 0;" ::: "memory");
    __syncthreads();

    uint32_t qh[4][4];
    {
        const int ar = wid * 16 + (lane & 15);
        const uint32_t ab = (uint32_t)((lane >> 4) << 4);
#pragma unroll
        for (int ks = 0; ks < 4; ks++) {
            uint32_t base = (uint32_t)(ar * FA_RS) + ab + ks * 32;
            ldsm_x4(qh[ks][0], qh[ks][1], qh[ks][2], qh[ks][3], su + base);
        }
    }
    __syncthreads();

    float O[8][4];
#pragma unroll
    for (int t = 0; t < 8; t++)
#pragma unroll
        for (int f = 0; f < 4; f++) O[t][f] = 0.f;
    float m0 = -1e30f, m1 = -1e30f, l0 = 0.f, l1 = 0.f;

    fa_load_stage(su, tid, K, V, 0);
    fa_load_stage(su, tid, K, V, 1);
    fa_load_stage(su, tid, K, V, 2);

    const int kb_row = (lane & 7) | ((lane & 16) >> 1);
    const uint32_t kb_off = (uint32_t)((lane & 8) << 1);
    const int v_row = lane & 15;
    const uint32_t v_off = (uint32_t)(((lane & 16) >> 4) * 16);

    for (int blk = 0; blk < nblk; blk++) {
        asm volatile("cp.async.wait_group 2;" ::: "memory");
        __syncthreads();
        if (blk + 3 < nblk) fa_load_stage(su, tid, K, V, blk + 3);
        else asm volatile("cp.async.commit_group;");   // empty group keeps count uniform

        const uint32_t sb = su + (uint32_t)(blk & (FA_NST - 1)) * FA_STAGE;

        float S[8][4];
#pragma unroll
        for (int t = 0; t < 8; t++)
#pragma unroll
            for (int f = 0; f < 4; f++) S[t][f] = 0.f;

#pragma unroll
        for (int ks = 0; ks < 4; ks++) {
            uint32_t kh[4][4];
#pragma unroll
            for (int np = 0; np < 4; np++) {
                uint32_t base = (uint32_t)((np * 16 + kb_row) * FA_RS) + kb_off + ks * 32;
                ldsm_x4(kh[np][0], kh[np][1], kh[np][2], kh[np][3], sb + base);
            }
#pragma unroll
            for (int np = 0; np < 4; np++) {
                mma_f16(S[2 * np],     qh[ks], &kh[np][0]);
                mma_f16(S[2 * np + 1], qh[ks], &kh[np][2]);
            }
        }

        const int jbase = blk * 64;
        float mx0 = -1e30f, mx1 = -1e30f;
#pragma unroll
        for (int t = 0; t < 8; t++) {
            int c0 = t * 8 + (lane & 3) * 2;
            float k0m = (jbase + c0     < nv) ? 0.f : -1e30f;
            float k1m = (jbase + c0 + 1 < nv) ? 0.f : -1e30f;
            S[t][0] = S[t][0] * FA_SCL + k0m;
            S[t][1] = S[t][1] * FA_SCL + k1m;
            S[t][2] = S[t][2] * FA_SCL + k0m;
            S[t][3] = S[t][3] * FA_SCL + k1m;
            mx0 = fmaxf(mx0, fmaxf(S[t][0], S[t][1]));
            mx1 = fmaxf(mx1, fmaxf(S[t][2], S[t][3]));
        }
#pragma unroll
        for (int off = 1; off <= 2; off <<= 1) {
            mx0 = fmaxf(mx0, __shfl_xor_sync(0xffffffffu, mx0, off));
            mx1 = fmaxf(mx1, __shfl_xor_sync(0xffffffffu, mx1, off));
        }
        float mn0 = fmaxf(m0, mx0), mn1 = fmaxf(m1, mx1);
        float al0 = ex2(m0 - mn0), al1 = ex2(m1 - mn1);
        m0 = mn0; m1 = mn1;
        float s0 = 0.f, s1 = 0.f;
#pragma unroll
        for (int t = 0; t < 8; t++) {
            S[t][0] = ex2(S[t][0] - mn0);
            S[t][1] = ex2(S[t][1] - mn0);
            S[t][2] = ex2(S[t][2] - mn1);
            S[t][3] = ex2(S[t][3] - mn1);
            s0 += S[t][0] + S[t][1];
            s1 += S[t][2] + S[t][3];
        }
#pragma unroll
        for (int off = 1; off <= 2; off <<= 1) {
            s0 += __shfl_xor_sync(0xffffffffu, s0, off);
            s1 += __shfl_xor_sync(0xffffffffu, s1, off);
        }
        l0 = l0 * al0 + s0;
        l1 = l1 * al1 + s1;
#pragma unroll
        for (int t = 0; t < 8; t++) {
            O[t][0] *= al0; O[t][1] *= al0;
            O[t][2] *= al1; O[t][3] *= al1;
        }

        uint32_t ph[4][4];
#pragma unroll
        for (int s = 0; s < 4; s++) {
#pragma unroll
            for (int half_i = 0; half_i < 2; half_i++) {
#pragma unroll
                for (int rr = 0; rr < 2; rr++) {
                    float p0 = S[2 * s + half_i][rr * 2 + 0];
                    float p1 = S[2 * s + half_i][rr * 2 + 1];
                    __half2 vh = __floats2half2_rn(p0, p1);
                    ph[s][half_i * 2 + rr] = *reinterpret_cast<uint32_t*>(&vh);
                }
            }
        }

#pragma unroll
        for (int s = 0; s < 4; s++) {
            uint32_t vh[4][4];
#pragma unroll
            for (int np = 0; np < 4; np++) {
                uint32_t base = (uint32_t)((16 * s + v_row) * FA_RS) + np * 32 + v_off;
                ldsm_x4_t(vh[np][0], vh[np][1], vh[np][2], vh[np][3], sb + FA_ARR + base);
            }
#pragma unroll
            for (int np = 0; np < 4; np++) {
                mma_f16(O[2 * np],     ph[s], &vh[np][0]);
                mma_f16(O[2 * np + 1], ph[s], &vh[np][2]);
            }
        }
    }

    const float inv0 = 1.0f / l0, inv1 = 1.0f / l1;
    const int r0 = q0 + wid * 16 + (lane >> 2);
    __half2* c2 = reinterpret_cast<__half2*>(g_c);
#pragma unroll
    for (int t = 0; t < 8; t++) {
        int d = t * 8 + (lane & 3) * 2;
        size_t di0 = (((size_t)(b * NTOK + r0) * CDIM) + h * 64 + d) >> 1;
        size_t di1 = (((size_t)(b * NTOK + r0 + 8) * CDIM) + h * 64 + d) >> 1;
        c2[di0] = __floats2half2_rn(O[t][0] * inv0, O[t][1] * inv0);
        c2[di1] = __floats2half2_rn(O[t][2] * inv1, O[t][3] * inv1);
    }
}

// ---------------- launch ----------------
extern "C" void kernel_launch(void* const* d_in, const int* in_sizes, int n_in,
                              void* d_out, int out_size)
{
    (void)in_sizes; (void)n_in; (void)out_size;
    const float* x    = (const float*)d_in[0];
    const int*   mask = (const int*)d_in[1];
    const float* Wqkv = (const float*)d_in[2];
    const float* bqkv = (const float*)d_in[3];
    const float* Aqkv = (const float*)d_in[4];
    const float* Bqkv = (const float*)d_in[5];
    const float* Wp   = (const float*)d_in[6];
    const float* bp   = (const float*)d_in[7];
    const float* Ap   = (const float*)d_in[8];
    const float* Bp   = (const float*)d_in[9];
    float* out = (float*)d_out;

    fuse_qkv_kernel<<<(QKVC * CDIM + 255) / 256, 256>>>(Wqkv, Bqkv, Aqkv);
    fuse_p_kernel<<<(CDIM * CDIM + 255) / 256, 256>>>(Wp, Bp, Ap);
    cvt_x_kernel<<<(MROWS * CDIM + 255) / 256, 256>>>(x);
    scan_mask_kernel<<<BATCH, 256>>>(mask);
    gather_x_kernel<<<dim3(NTOK, BATCH), 128>>>();

    cudaFuncSetAttribute(mma_gemm_q, cudaFuncAttributeMaxDynamicSharedMemorySize, GM_SMEM);
    mma_gemm_q<<<dim3(CDIM / 128, MROWS / 128), 256, GM_SMEM>>>(bqkv);

    cudaFuncSetAttribute(mma_gemm_kv, cudaFuncAttributeMaxDynamicSharedMemorySize, GM_SMEM);
    mma_gemm_kv<<<dim3(2 * CDIM / 128, BATCH * NTOK / 128), 256, GM_SMEM>>>(bqkv);

    cudaFuncSetAttribute(flash_mma_kernel, cudaFuncAttributeMaxDynamicSharedMemorySize, FA_SMEM);
    flash_mma_kernel<<<dim3(NTOK / 128, HEADS, BATCH), 256, FA_SMEM>>>();

    cudaFuncSetAttribute(mma_gemm_proj, cudaFuncAttributeMaxDynamicSharedMemorySize, GM_SMEM);
    mma_gemm_proj<<<dim3(CDIM / 128, MROWS / 128), 256, GM_SMEM>>>(bp, out);
}